// round 2
// baseline (speedup 1.0000x reference)
#include <cuda_runtime.h>
#include <math.h>

// Problem constants (fixed by setup_inputs)
#define B_  4
#define L_  4096
#define DM  512
#define H_  8
#define P_  4
#define D_  64
#define MTOT (B_*L_)   // 16384

// Scratch (no cudaMalloc allowed)
__device__ float g_q[(size_t)MTOT*DM];
__device__ float g_k[(size_t)MTOT*DM];
__device__ float g_v[(size_t)MTOT*DM];
__device__ float g_attn[(size_t)MTOT*DM];
__device__ float g_off[(size_t)MTOT*(H_*P_)];
__device__ float g_logit[(size_t)MTOT*(H_*P_)];

// ---------------------------------------------------------------------------
// C[M,N] = A[M,K] @ W[N,K]^T + bias[N]   (both operands K-contiguous, "NT")
// Tile: 128x128x16, 256 threads, 8x8 per-thread microtile.
// M multiple of 128, K multiple of 16. N guarded (handles N=32).
// ---------------------------------------------------------------------------
__global__ __launch_bounds__(256) void sgemm_nt(
    const float* __restrict__ A, const float* __restrict__ W,
    const float* __restrict__ bias, float* __restrict__ C,
    int M, int N, int K)
{
    __shared__ float As[16][128];
    __shared__ float Bs[16][128];

    const int tid = threadIdx.x;
    const int m0 = blockIdx.y * 128;
    const int n0 = blockIdx.x * 128;
    const int tx = tid & 15;        // 0..15  -> n
    const int ty = tid >> 4;        // 0..15  -> m

    float acc[8][8];
#pragma unroll
    for (int i = 0; i < 8; i++)
#pragma unroll
        for (int j = 0; j < 8; j++) acc[i][j] = 0.f;

    for (int k0 = 0; k0 < K; k0 += 16) {
        // Load A tile (128 rows x 16 cols) as float4, store transposed
#pragma unroll
        for (int t = 0; t < 2; t++) {
            int e   = tid + t * 256;     // 0..511 float4 slots
            int row = e >> 2;
            int c4  = e & 3;
            float4 val = *(const float4*)(A + (size_t)(m0 + row) * K + k0 + c4 * 4);
            As[c4 * 4 + 0][row] = val.x;
            As[c4 * 4 + 1][row] = val.y;
            As[c4 * 4 + 2][row] = val.z;
            As[c4 * 4 + 3][row] = val.w;
        }
        // Load W tile (128 rows x 16 cols), rows past N are zero
#pragma unroll
        for (int t = 0; t < 2; t++) {
            int e   = tid + t * 256;
            int row = e >> 2;
            int c4  = e & 3;
            float4 val = make_float4(0.f, 0.f, 0.f, 0.f);
            if (n0 + row < N)
                val = *(const float4*)(W + (size_t)(n0 + row) * K + k0 + c4 * 4);
            Bs[c4 * 4 + 0][row] = val.x;
            Bs[c4 * 4 + 1][row] = val.y;
            Bs[c4 * 4 + 2][row] = val.z;
            Bs[c4 * 4 + 3][row] = val.w;
        }
        __syncthreads();

#pragma unroll
        for (int kk = 0; kk < 16; kk++) {
            float a[8], b[8];
            // vectorized shared loads
            *(float4*)&a[0] = *(const float4*)&As[kk][ty * 8 + 0];
            *(float4*)&a[4] = *(const float4*)&As[kk][ty * 8 + 4];
            *(float4*)&b[0] = *(const float4*)&Bs[kk][tx * 8 + 0];
            *(float4*)&b[4] = *(const float4*)&Bs[kk][tx * 8 + 4];
#pragma unroll
            for (int i = 0; i < 8; i++)
#pragma unroll
                for (int j = 0; j < 8; j++)
                    acc[i][j] = fmaf(a[i], b[j], acc[i][j]);
        }
        __syncthreads();
    }

    // Epilogue: add bias, store
#pragma unroll
    for (int i = 0; i < 8; i++) {
        int m = m0 + ty * 8 + i;
#pragma unroll
        for (int j = 0; j < 8; j++) {
            int n = n0 + tx * 8 + j;
            if (n < N) C[(size_t)m * N + n] = acc[i][j] + bias[n];
        }
    }
}

// ---------------------------------------------------------------------------
// Deformable attention core. One warp per (b, l, h); each lane owns a float2
// of the D=64 head dim (d = 2*lane, 2*lane+1).
// q,k,v,out layout: [B*L, H*D] row-major. off/logit: [B*L, H*P].
// ---------------------------------------------------------------------------
__global__ __launch_bounds__(256) void attn_kernel(
    const float* __restrict__ q, const float* __restrict__ k,
    const float* __restrict__ v, const float* __restrict__ off,
    const float* __restrict__ lgt, float* __restrict__ out)
{
    const int gw   = (blockIdx.x * blockDim.x + threadIdx.x) >> 5;
    const int lane = threadIdx.x & 31;
    const int h    = gw & (H_ - 1);
    const int bl   = gw >> 3;          // b*L + l
    const int l    = bl & (L_ - 1);
    const int brow = bl - l;           // b*L

    const size_t qoff = (size_t)bl * DM + h * D_ + 2 * lane;
    const float2 qd = *(const float2*)(q + qoff);
    const float* op = off + (size_t)bl * (H_ * P_) + h * P_;
    const float* lp = lgt + (size_t)bl * (H_ * P_) + h * P_;

    float  dots[P_];
    float2 vs[P_];

#pragma unroll
    for (int p = 0; p < P_; p++) {
        float pos = (float)l + op[p];
        pos = fminf(fmaxf(pos, 0.f), (float)(L_ - 1));
        float fi = floorf(pos);
        int   i0 = (int)fi;
        int   i1 = min(i0 + 1, L_ - 1);
        float w  = pos - fi;

        size_t o0 = (size_t)(brow + i0) * DM + h * D_ + 2 * lane;
        size_t o1 = (size_t)(brow + i1) * DM + h * D_ + 2 * lane;
        float2 k0 = *(const float2*)(k + o0);
        float2 k1 = *(const float2*)(k + o1);
        float2 v0 = *(const float2*)(v + o0);
        float2 v1 = *(const float2*)(v + o1);

        float2 ks;
        ks.x = (1.f - w) * k0.x + w * k1.x;
        ks.y = (1.f - w) * k0.y + w * k1.y;
        vs[p].x = (1.f - w) * v0.x + w * v1.x;
        vs[p].y = (1.f - w) * v0.y + w * v1.y;

        float d = qd.x * ks.x + qd.y * ks.y;
#pragma unroll
        for (int s = 16; s > 0; s >>= 1)
            d += __shfl_xor_sync(0xffffffffu, d, s);
        dots[p] = d;
    }

    // softmax over P=4 (scale = 1/sqrt(64) = 0.125)
    float s0 = dots[0] * 0.125f + lp[0];
    float s1 = dots[1] * 0.125f + lp[1];
    float s2 = dots[2] * 0.125f + lp[2];
    float s3 = dots[3] * 0.125f + lp[3];
    float m  = fmaxf(fmaxf(s0, s1), fmaxf(s2, s3));
    float e0 = expf(s0 - m), e1 = expf(s1 - m);
    float e2 = expf(s2 - m), e3 = expf(s3 - m);
    float inv = 1.f / (e0 + e1 + e2 + e3);

    float2 o;
    o.x = (e0 * vs[0].x + e1 * vs[1].x + e2 * vs[2].x + e3 * vs[3].x) * inv;
    o.y = (e0 * vs[0].y + e1 * vs[1].y + e2 * vs[2].y + e3 * vs[3].y) * inv;
    *(float2*)(out + qoff) = o;
}

// ---------------------------------------------------------------------------
extern "C" void kernel_launch(void* const* d_in, const int* in_sizes, int n_in,
                              void* d_out, int out_size)
{
    const float* q_in  = (const float*)d_in[0];
    const float* kv_in = (const float*)d_in[1];
    const float* Wq    = (const float*)d_in[2];
    const float* bq    = (const float*)d_in[3];
    const float* Wk    = (const float*)d_in[4];
    const float* bk    = (const float*)d_in[5];
    const float* Wv    = (const float*)d_in[6];
    const float* bv    = (const float*)d_in[7];
    const float* Woff  = (const float*)d_in[8];
    const float* boff  = (const float*)d_in[9];
    const float* Wa    = (const float*)d_in[10];
    const float* ba    = (const float*)d_in[11];
    const float* Wo    = (const float*)d_in[12];
    const float* bo    = (const float*)d_in[13];

    float *qb, *kb, *vb, *ab, *ofb, *lgb;
    cudaGetSymbolAddress((void**)&qb,  g_q);
    cudaGetSymbolAddress((void**)&kb,  g_k);
    cudaGetSymbolAddress((void**)&vb,  g_v);
    cudaGetSymbolAddress((void**)&ab,  g_attn);
    cudaGetSymbolAddress((void**)&ofb, g_off);
    cudaGetSymbolAddress((void**)&lgb, g_logit);

    const int M = MTOT, K = DM;
    dim3 blk(256);
    dim3 gBig(DM / 128, M / 128);   // N = 512
    dim3 gSm(1, M / 128);           // N = 32

    // Projections
    sgemm_nt<<<gBig, blk>>>(q_in,  Wq,   bq,   qb,  M, DM, K);
    sgemm_nt<<<gBig, blk>>>(kv_in, Wk,   bk,   kb,  M, DM, K);
    sgemm_nt<<<gBig, blk>>>(kv_in, Wv,   bv,   vb,  M, DM, K);
    sgemm_nt<<<gSm,  blk>>>(q_in,  Woff, boff, ofb, M, H_ * P_, K);
    sgemm_nt<<<gSm,  blk>>>(q_in,  Wa,   ba,   lgb, M, H_ * P_, K);

    // Deformable attention: M*H warps, 8 warps/block
    attn_kernel<<<(M * H_) / 8, blk>>>(qb, kb, vb, ofb, lgb, ab);

    // Output projection straight into d_out
    sgemm_nt<<<gBig, blk>>>(ab, Wo, bo, (float*)d_out, M, DM, K);
}

// round 5
// speedup vs baseline: 3.0018x; 3.0018x over previous
#include <cuda_runtime.h>
#include <math.h>
#include <stdint.h>

// Problem constants (fixed by setup_inputs)
#define B_  4
#define L_  4096
#define DM  512
#define H_  8
#define P_  4
#define D_  64
#define MTOT (B_*L_)   // 16384

// GEMM tiling
#define BM 128
#define BN 128
#define BK 32
#define NSTAGES 4
#define KTILES (DM/BK)          // 16
#define LDSA (BK + 4)           // 36 floats per smem row (conflict-free, 16B aligned)
#define ATILE (BM * LDSA)       // floats
#define BTILE (BN * LDSA)
#define STAGEF (ATILE + BTILE)  // 9216 floats per stage
#define DYN_SMEM (NSTAGES * STAGEF * 4)  // 147456 B

// Scratch (no cudaMalloc allowed)
__device__ float g_q   [(size_t)MTOT*DM];
__device__ float g_k   [(size_t)MTOT*DM];
__device__ float g_v   [(size_t)MTOT*DM];
__device__ float g_attn[(size_t)MTOT*DM];
__device__ float g_ofa [(size_t)MTOT*64];   // fused offsets|logits, stride 64
__device__ float g_Wofa[64*DM];             // Woff (rows 0..31) | Wa (rows 32..63)
__device__ float g_bofa[64];                // boff | ba

// ---------------------------------------------------------------------------
__device__ __forceinline__ uint32_t smem_u32(const void* p) {
    uint32_t a;
    asm("{ .reg .u64 t; cvta.to.shared.u64 t, %1; cvt.u32.u64 %0, t; }"
        : "=r"(a) : "l"(p));
    return a;
}

__device__ __forceinline__ void cp16(uint32_t dst, const float* src, uint32_t sz) {
    // sz=16 copies 16B, sz=0 zero-fills 16B
    asm volatile("cp.async.cg.shared.global [%0], [%1], 16, %2;\n"
                 :: "r"(dst), "l"(src), "r"(sz));
}

// round-to-nearest fp32 -> tf32 (zero-mean rounding error; truncation would bias)
__device__ __forceinline__ uint32_t f2tf(float x) {
    uint32_t r;
    asm("cvt.rna.tf32.f32 %0, %1;" : "=r"(r) : "f"(x));
    return r;
}

__device__ __forceinline__ void mma_tf32(float* c, const uint32_t* a, const uint32_t* b) {
    asm volatile(
        "mma.sync.aligned.m16n8k8.row.col.f32.tf32.tf32.f32 "
        "{%0,%1,%2,%3}, {%4,%5,%6,%7}, {%8,%9}, {%0,%1,%2,%3};"
        : "+f"(c[0]), "+f"(c[1]), "+f"(c[2]), "+f"(c[3])
        : "r"(a[0]), "r"(a[1]), "r"(a[2]), "r"(a[3]), "r"(b[0]), "r"(b[1]));
}

// ---------------------------------------------------------------------------
// C[M,N] = A[M,512] @ W[N,512]^T + bias[N] via mma.sync tf32.
// CTA: 128x128 tile, 256 threads = 8 warps (4 m x 2 n), warp tile 32x64.
// cp.async 4-stage pipeline. N <= BN handled by zero-fill + store guards.
// ---------------------------------------------------------------------------
__global__ __launch_bounds__(256, 1) void gemm_tf32(
    const float* __restrict__ A, const float* __restrict__ W,
    const float* __restrict__ bias, float* __restrict__ C, int N)
{
    extern __shared__ float sm[];

    const int tid    = threadIdx.x;
    const int lane   = tid & 31;
    const int wid    = tid >> 5;
    const int warp_m = wid >> 1;     // 0..3 -> m offset *32
    const int warp_n = wid & 1;      // 0..1 -> n offset *64
    const int m0     = blockIdx.y * BM;
    const int n0     = blockIdx.x * BN;
    const int r      = lane >> 2;    // 0..7
    const int c      = lane & 3;     // 0..3

    float acc[2][8][4];
#pragma unroll
    for (int i = 0; i < 2; i++)
#pragma unroll
        for (int j = 0; j < 8; j++)
#pragma unroll
            for (int q = 0; q < 4; q++) acc[i][j][q] = 0.f;

    const uint32_t smb = smem_u32(sm);

    auto load_tile = [&](int t) {
        const int s = t & (NSTAGES - 1);
        const uint32_t sa = smb + (uint32_t)(s * STAGEF) * 4u;
        const uint32_t sb = sa + (uint32_t)ATILE * 4u;
        const int k0 = t * BK;
#pragma unroll
        for (int i = 0; i < 4; i++) {
            const int idx = tid + i * 256;       // 0..1023
            const int row = idx >> 3;            // 0..127
            const int kc  = (idx & 7) * 4;       // 0,4,..28
            cp16(sa + (uint32_t)(row * LDSA + kc) * 4u,
                 A + (size_t)(m0 + row) * DM + k0 + kc, 16u);
            const int wr = n0 + row;
            const float* bsrc = W + (size_t)(wr < N ? wr : 0) * DM + k0 + kc;
            cp16(sb + (uint32_t)(row * LDSA + kc) * 4u, bsrc, wr < N ? 16u : 0u);
        }
        asm volatile("cp.async.commit_group;\n");
    };

    // prologue: stages 0..2
#pragma unroll
    for (int t = 0; t < NSTAGES - 1; t++) load_tile(t);

    for (int t = 0; t < KTILES; t++) {
        asm volatile("cp.async.wait_group %0;\n" :: "n"(NSTAGES - 2));
        __syncthreads();

        // prefetch tile t+3 into stage (t-1)&3 (consumed last iteration)
        if (t + NSTAGES - 1 < KTILES) load_tile(t + NSTAGES - 1);
        else asm volatile("cp.async.commit_group;\n");

        const float* sA = sm + (t & (NSTAGES - 1)) * STAGEF;
        const float* sB = sA + ATILE;
        const float* aBase = sA + (warp_m * 32 + r) * LDSA + c;
        const float* bBase = sB + (warp_n * 64 + r) * LDSA + c;

#pragma unroll
        for (int ks = 0; ks < 4; ks++) {
            const int k0 = ks * 8;
            uint32_t af[2][4];
#pragma unroll
            for (int mf = 0; mf < 2; mf++) {
                af[mf][0] = f2tf(aBase[(mf * 16    ) * LDSA + k0    ]);
                af[mf][1] = f2tf(aBase[(mf * 16 + 8) * LDSA + k0    ]);
                af[mf][2] = f2tf(aBase[(mf * 16    ) * LDSA + k0 + 4]);
                af[mf][3] = f2tf(aBase[(mf * 16 + 8) * LDSA + k0 + 4]);
            }
#pragma unroll
            for (int nf = 0; nf < 8; nf++) {
                uint32_t bf[2];
                bf[0] = f2tf(bBase[nf * 8 * LDSA + k0    ]);
                bf[1] = f2tf(bBase[nf * 8 * LDSA + k0 + 4]);
                mma_tf32(acc[0][nf], af[0], bf);
                mma_tf32(acc[1][nf], af[1], bf);
            }
        }
        __syncthreads();
    }

    // epilogue: bias + store as float2 pairs
#pragma unroll
    for (int mf = 0; mf < 2; mf++) {
        const int row0 = m0 + warp_m * 32 + mf * 16 + r;
#pragma unroll
        for (int nf = 0; nf < 8; nf++) {
            const int col = n0 + warp_n * 64 + nf * 8 + c * 2;
            if (col < N) {
                const float bx = bias[col], by = bias[col + 1];
                float2 o0 = make_float2(acc[mf][nf][0] + bx, acc[mf][nf][1] + by);
                float2 o1 = make_float2(acc[mf][nf][2] + bx, acc[mf][nf][3] + by);
                *(float2*)(C + (size_t)row0 * N + col)       = o0;
                *(float2*)(C + (size_t)(row0 + 8) * N + col) = o1;
            }
        }
    }
}

// ---------------------------------------------------------------------------
// Deformable attention core. One warp per (b, l, h); each lane owns a float2
// of the D=64 head dim. ofa layout: [B*L, 64] = offsets(0..31) | logits(32..63).
// ---------------------------------------------------------------------------
__global__ __launch_bounds__(256) void attn_kernel(
    const float* __restrict__ q, const float* __restrict__ k,
    const float* __restrict__ v, const float* __restrict__ ofa,
    float* __restrict__ out)
{
    const int gw   = (blockIdx.x * blockDim.x + threadIdx.x) >> 5;
    const int lane = threadIdx.x & 31;
    const int h    = gw & (H_ - 1);
    const int bl   = gw >> 3;          // b*L + l
    const int l    = bl & (L_ - 1);
    const int brow = bl - l;           // b*L

    const size_t qoff = (size_t)bl * DM + h * D_ + 2 * lane;
    const float2 qd = *(const float2*)(q + qoff);
    const float* op = ofa + (size_t)bl * 64 + h * P_;
    const float* lp = op + 32;

    float  dots[P_];
    float2 vs[P_];

#pragma unroll
    for (int p = 0; p < P_; p++) {
        float pos = (float)l + op[p];
        pos = fminf(fmaxf(pos, 0.f), (float)(L_ - 1));
        float fi = floorf(pos);
        int   i0 = (int)fi;
        int   i1 = min(i0 + 1, L_ - 1);
        float w  = pos - fi;

        size_t o0 = (size_t)(brow + i0) * DM + h * D_ + 2 * lane;
        size_t o1 = (size_t)(brow + i1) * DM + h * D_ + 2 * lane;
        float2 k0 = *(const float2*)(k + o0);
        float2 k1 = *(const float2*)(k + o1);
        float2 v0 = *(const float2*)(v + o0);
        float2 v1 = *(const float2*)(v + o1);

        float2 ks;
        ks.x = (1.f - w) * k0.x + w * k1.x;
        ks.y = (1.f - w) * k0.y + w * k1.y;
        vs[p].x = (1.f - w) * v0.x + w * v1.x;
        vs[p].y = (1.f - w) * v0.y + w * v1.y;

        float d = qd.x * ks.x + qd.y * ks.y;
#pragma unroll
        for (int s = 16; s > 0; s >>= 1)
            d += __shfl_xor_sync(0xffffffffu, d, s);
        dots[p] = d;
    }

    float s0 = dots[0] * 0.125f + lp[0];
    float s1 = dots[1] * 0.125f + lp[1];
    float s2 = dots[2] * 0.125f + lp[2];
    float s3 = dots[3] * 0.125f + lp[3];
    float m  = fmaxf(fmaxf(s0, s1), fmaxf(s2, s3));
    float e0 = expf(s0 - m), e1 = expf(s1 - m);
    float e2 = expf(s2 - m), e3 = expf(s3 - m);
    float inv = 1.f / (e0 + e1 + e2 + e3);

    float2 o;
    o.x = (e0 * vs[0].x + e1 * vs[1].x + e2 * vs[2].x + e3 * vs[3].x) * inv;
    o.y = (e0 * vs[0].y + e1 * vs[1].y + e2 * vs[2].y + e3 * vs[3].y) * inv;
    *(float2*)(out + qoff) = o;
}

// ---------------------------------------------------------------------------
extern "C" void kernel_launch(void* const* d_in, const int* in_sizes, int n_in,
                              void* d_out, int out_size)
{
    const float* q_in  = (const float*)d_in[0];
    const float* kv_in = (const float*)d_in[1];
    const float* Wq    = (const float*)d_in[2];
    const float* bq    = (const float*)d_in[3];
    const float* Wk    = (const float*)d_in[4];
    const float* bk    = (const float*)d_in[5];
    const float* Wv    = (const float*)d_in[6];
    const float* bv    = (const float*)d_in[7];
    const float* Woff  = (const float*)d_in[8];
    const float* boff  = (const float*)d_in[9];
    const float* Wa    = (const float*)d_in[10];
    const float* ba    = (const float*)d_in[11];
    const float* Wo    = (const float*)d_in[12];
    const float* bo    = (const float*)d_in[13];

    float *qb, *kb, *vb, *ab, *ofab, *wofa, *bofa;
    cudaGetSymbolAddress((void**)&qb,   g_q);
    cudaGetSymbolAddress((void**)&kb,   g_k);
    cudaGetSymbolAddress((void**)&vb,   g_v);
    cudaGetSymbolAddress((void**)&ab,   g_attn);
    cudaGetSymbolAddress((void**)&ofab, g_ofa);
    cudaGetSymbolAddress((void**)&wofa, g_Wofa);
    cudaGetSymbolAddress((void**)&bofa, g_bofa);

    cudaFuncSetAttribute(gemm_tf32,
                         cudaFuncAttributeMaxDynamicSharedMemorySize, DYN_SMEM);

    // Concatenate Woff|Wa and boff|ba (device-to-device, capturable)
    cudaMemcpyAsync(wofa,           Woff, 32 * DM * 4, cudaMemcpyDeviceToDevice);
    cudaMemcpyAsync(wofa + 32 * DM, Wa,   32 * DM * 4, cudaMemcpyDeviceToDevice);
    cudaMemcpyAsync(bofa,           boff, 32 * 4,      cudaMemcpyDeviceToDevice);
    cudaMemcpyAsync(bofa + 32,      ba,   32 * 4,      cudaMemcpyDeviceToDevice);

    dim3 blk(256);
    dim3 gBig(DM / BN, MTOT / BM);   // (4, 128) = 512 CTAs
    dim3 gOfa(1, MTOT / BM);         // (1, 128), N=64

    gemm_tf32<<<gBig, blk, DYN_SMEM>>>(q_in,  Wq,   bq,   qb,   DM);
    gemm_tf32<<<gBig, blk, DYN_SMEM>>>(kv_in, Wk,   bk,   kb,   DM);
    gemm_tf32<<<gBig, blk, DYN_SMEM>>>(kv_in, Wv,   bv,   vb,   DM);
    gemm_tf32<<<gOfa, blk, DYN_SMEM>>>(q_in,  wofa, bofa, ofab, 64);

    attn_kernel<<<(MTOT * H_) / 8, 256>>>(qb, kb, vb, ofab, ab);

    gemm_tf32<<<gBig, blk, DYN_SMEM>>>(ab, Wo, bo, (float*)d_out, DM);
}

// round 8
// speedup vs baseline: 3.6313x; 1.2097x over previous
#include <cuda_runtime.h>
#include <math.h>
#include <stdint.h>

// Problem constants (fixed by setup_inputs)
#define B_  4
#define L_  4096
#define DM  512
#define H_  8
#define P_  4
#define D_  64
#define MTOT (B_*L_)   // 16384

#define NQOA 576       // Wq | Woff | Wa fused output cols
#define NKV  1024      // Wk | Wv fused output cols

// GEMM tiling
#define BM 128
#define BN 128
#define BK 32
#define NSTAGES 3
#define KTILES (DM/BK)          // 16
#define LDSA (BK + 4)           // 36 floats per smem row (conflict-free)
#define ATILE (BM * LDSA)
#define BTILE (BN * LDSA)
#define STAGEF (ATILE + BTILE)  // 9216 floats
#define DYN_SMEM (NSTAGES * STAGEF * 4)  // 110592 B -> 2 CTAs/SM

// Scratch (no cudaMalloc allowed)
__device__ float g_qoa [(size_t)MTOT*NQOA];  // q (0..511) | offsets (512..543) | logits (544..575)
__device__ float g_kv  [(size_t)MTOT*NKV];   // k (0..511) | v (512..1023)
__device__ float g_attn[(size_t)MTOT*DM];    // attn output (tf32 bits)
__device__ float g_Wqoa[640*DM];             // fused + padded weight (tf32 bits)
__device__ float g_Wkv [NKV*DM];
__device__ float g_Wo_t[DM*DM];
__device__ float g_bqoa[640];
__device__ float g_bkv [NKV];

// ---------------------------------------------------------------------------
__device__ __forceinline__ uint32_t smem_u32(const void* p) {
    uint32_t a;
    asm("{ .reg .u64 t; cvta.to.shared.u64 t, %1; cvt.u32.u64 %0, t; }"
        : "=r"(a) : "l"(p));
    return a;
}

__device__ __forceinline__ void cp16(uint32_t dst, const float* src, uint32_t sz) {
    asm volatile("cp.async.cg.shared.global [%0], [%1], 16, %2;\n"
                 :: "r"(dst), "l"(src), "r"(sz));
}

// round-to-nearest fp32 -> tf32 (zero-mean rounding error)
__device__ __forceinline__ uint32_t f2tf(float x) {
    uint32_t r;
    asm("cvt.rna.tf32.f32 %0, %1;" : "=r"(r) : "f"(x));
    return r;
}

__device__ __forceinline__ void mma_tf32(float* c, const uint32_t* a, const uint32_t* b) {
    asm volatile(
        "mma.sync.aligned.m16n8k8.row.col.f32.tf32.tf32.f32 "
        "{%0,%1,%2,%3}, {%4,%5,%6,%7}, {%8,%9}, {%0,%1,%2,%3};"
        : "+f"(c[0]), "+f"(c[1]), "+f"(c[2]), "+f"(c[3])
        : "r"(a[0]), "r"(a[1]), "r"(a[2]), "r"(a[3]), "r"(b[0]), "r"(b[1]));
}

// convert-copy: dst[i] = tf32_bits(src[i])
__global__ void convcpy(float* __restrict__ dst, const float* __restrict__ src, int n) {
    int i = blockIdx.x * blockDim.x + threadIdx.x;
    if (i < n) dst[i] = __uint_as_float(f2tf(src[i]));
}

// ---------------------------------------------------------------------------
// C[M,N] = A[M,512] @ W[N,512]^T + bias[N] via mma.sync tf32.
// CTA: 128x128 tile, 256 threads = 8 warps (4m x 2n), warp tile 32x64.
// cp.async 3-stage pipeline, 2 CTAs/SM. W must be pre-converted tf32 bits.
// CONVA: convert A fragments (false if A already tf32 bits).
// ---------------------------------------------------------------------------
template<bool CONVA>
__global__ __launch_bounds__(256, 2) void gemm_tf32(
    const float* __restrict__ A, const float* __restrict__ W,
    const float* __restrict__ bias, float* __restrict__ C, int N)
{
    extern __shared__ float sm[];

    const int tid    = threadIdx.x;
    const int lane   = tid & 31;
    const int wid    = tid >> 5;
    const int warp_m = wid >> 1;
    const int warp_n = wid & 1;
    const int m0     = blockIdx.y * BM;
    const int n0     = blockIdx.x * BN;
    const int r      = lane >> 2;
    const int c      = lane & 3;

    float acc[2][8][4];
#pragma unroll
    for (int i = 0; i < 2; i++)
#pragma unroll
        for (int j = 0; j < 8; j++)
#pragma unroll
            for (int q = 0; q < 4; q++) acc[i][j][q] = 0.f;

    const uint32_t smb = smem_u32(sm);

    auto load_tile = [&](int t) {
        const int s = t % NSTAGES;
        const uint32_t sa = smb + (uint32_t)(s * STAGEF) * 4u;
        const uint32_t sb = sa + (uint32_t)ATILE * 4u;
        const int k0 = t * BK;
#pragma unroll
        for (int i = 0; i < 4; i++) {
            const int idx = tid + i * 256;
            const int row = idx >> 3;
            const int kc  = (idx & 7) * 4;
            cp16(sa + (uint32_t)(row * LDSA + kc) * 4u,
                 A + (size_t)(m0 + row) * DM + k0 + kc, 16u);
            const int wr = n0 + row;
            const float* bsrc = W + (size_t)(wr < N ? wr : 0) * DM + k0 + kc;
            cp16(sb + (uint32_t)(row * LDSA + kc) * 4u, bsrc, wr < N ? 16u : 0u);
        }
        asm volatile("cp.async.commit_group;\n");
    };

    // prologue: stages 0..1
#pragma unroll
    for (int t = 0; t < NSTAGES - 1; t++) load_tile(t);

    for (int t = 0; t < KTILES; t++) {
        asm volatile("cp.async.wait_group %0;\n" :: "n"(NSTAGES - 2));
        __syncthreads();

        if (t + NSTAGES - 1 < KTILES) load_tile(t + NSTAGES - 1);
        else asm volatile("cp.async.commit_group;\n");

        const float*    sA = sm + (t % NSTAGES) * STAGEF;
        const uint32_t* sB = (const uint32_t*)(sA + ATILE);
        const float*    aBase = sA + (warp_m * 32 + r) * LDSA + c;
        const uint32_t* bBase = sB + (warp_n * 64 + r) * LDSA + c;

#pragma unroll
        for (int ks = 0; ks < 4; ks++) {
            const int k0 = ks * 8;
            uint32_t af[2][4];
#pragma unroll
            for (int mf = 0; mf < 2; mf++) {
                if (CONVA) {
                    af[mf][0] = f2tf(aBase[(mf * 16    ) * LDSA + k0    ]);
                    af[mf][1] = f2tf(aBase[(mf * 16 + 8) * LDSA + k0    ]);
                    af[mf][2] = f2tf(aBase[(mf * 16    ) * LDSA + k0 + 4]);
                    af[mf][3] = f2tf(aBase[(mf * 16 + 8) * LDSA + k0 + 4]);
                } else {
                    const uint32_t* aU = (const uint32_t*)aBase;
                    af[mf][0] = aU[(mf * 16    ) * LDSA + k0    ];
                    af[mf][1] = aU[(mf * 16 + 8) * LDSA + k0    ];
                    af[mf][2] = aU[(mf * 16    ) * LDSA + k0 + 4];
                    af[mf][3] = aU[(mf * 16 + 8) * LDSA + k0 + 4];
                }
            }
#pragma unroll
            for (int nf = 0; nf < 8; nf++) {
                uint32_t bf[2];
                bf[0] = bBase[nf * 8 * LDSA + k0    ];
                bf[1] = bBase[nf * 8 * LDSA + k0 + 4];
                mma_tf32(acc[0][nf], af[0], bf);
                mma_tf32(acc[1][nf], af[1], bf);
            }
        }
        __syncthreads();
    }

    // epilogue: bias + store
#pragma unroll
    for (int mf = 0; mf < 2; mf++) {
        const int row0 = m0 + warp_m * 32 + mf * 16 + r;
#pragma unroll
        for (int nf = 0; nf < 8; nf++) {
            const int col = n0 + warp_n * 64 + nf * 8 + c * 2;
            if (col < N) {
                const float bx = bias[col], by = bias[col + 1];
                float2 o0 = make_float2(acc[mf][nf][0] + bx, acc[mf][nf][1] + by);
                float2 o1 = make_float2(acc[mf][nf][2] + bx, acc[mf][nf][3] + by);
                *(float2*)(C + (size_t)row0 * N + col)       = o0;
                *(float2*)(C + (size_t)(row0 + 8) * N + col) = o1;
            }
        }
    }
}

// ---------------------------------------------------------------------------
// Deformable attention. One warp per (b,l,h); lane owns a float2 of D=64.
// qoa: [M, 576] = q | offsets | logits.  kv: [M, 1024] = k | v.
// Output written as tf32-rounded bits (feeds the Wo GEMM with CONVA=false).
// ---------------------------------------------------------------------------
__global__ __launch_bounds__(256) void attn_kernel(
    const float* __restrict__ qoa, const float* __restrict__ kv,
    float* __restrict__ out)
{
    const int gw   = (blockIdx.x * blockDim.x + threadIdx.x) >> 5;
    const int lane = threadIdx.x & 31;
    const int h    = gw & (H_ - 1);
    const int bl   = gw >> 3;          // b*L + l
    const int l    = bl & (L_ - 1);
    const int brow = bl - l;           // b*L

    const float2 qd = *(const float2*)(qoa + (size_t)bl * NQOA + h * D_ + 2 * lane);
    const float* op = qoa + (size_t)bl * NQOA + 512 + h * P_;
    const float* lp = op + 32;

    float  dots[P_];
    float2 vs[P_];

#pragma unroll
    for (int p = 0; p < P_; p++) {
        float pos = (float)l + op[p];
        pos = fminf(fmaxf(pos, 0.f), (float)(L_ - 1));
        float fi = floorf(pos);
        int   i0 = (int)fi;
        int   i1 = min(i0 + 1, L_ - 1);
        float w  = pos - fi;

        const float* row0 = kv + (size_t)(brow + i0) * NKV + h * D_ + 2 * lane;
        const float* row1 = kv + (size_t)(brow + i1) * NKV + h * D_ + 2 * lane;
        float2 k0 = *(const float2*)(row0);
        float2 k1 = *(const float2*)(row1);
        float2 v0 = *(const float2*)(row0 + 512);
        float2 v1 = *(const float2*)(row1 + 512);

        float2 ks;
        ks.x = (1.f - w) * k0.x + w * k1.x;
        ks.y = (1.f - w) * k0.y + w * k1.y;
        vs[p].x = (1.f - w) * v0.x + w * v1.x;
        vs[p].y = (1.f - w) * v0.y + w * v1.y;

        float d = qd.x * ks.x + qd.y * ks.y;
#pragma unroll
        for (int s = 16; s > 0; s >>= 1)
            d += __shfl_xor_sync(0xffffffffu, d, s);
        dots[p] = d;
    }

    float s0 = dots[0] * 0.125f + lp[0];
    float s1 = dots[1] * 0.125f + lp[1];
    float s2 = dots[2] * 0.125f + lp[2];
    float s3 = dots[3] * 0.125f + lp[3];
    float m  = fmaxf(fmaxf(s0, s1), fmaxf(s2, s3));
    float e0 = expf(s0 - m), e1 = expf(s1 - m);
    float e2 = expf(s2 - m), e3 = expf(s3 - m);
    float inv = 1.f / (e0 + e1 + e2 + e3);

    float ox = (e0 * vs[0].x + e1 * vs[1].x + e2 * vs[2].x + e3 * vs[3].x) * inv;
    float oy = (e0 * vs[0].y + e1 * vs[1].y + e2 * vs[2].y + e3 * vs[3].y) * inv;
    float2 o = make_float2(__uint_as_float(f2tf(ox)), __uint_as_float(f2tf(oy)));
    *(float2*)(out + (size_t)bl * DM + h * D_ + 2 * lane) = o;
}

// ---------------------------------------------------------------------------
extern "C" void kernel_launch(void* const* d_in, const int* in_sizes, int n_in,
                              void* d_out, int out_size)
{
    const float* q_in  = (const float*)d_in[0];
    const float* kv_in = (const float*)d_in[1];
    const float* Wq    = (const float*)d_in[2];
    const float* bq    = (const float*)d_in[3];
    const float* Wk    = (const float*)d_in[4];
    const float* bk    = (const float*)d_in[5];
    const float* Wv    = (const float*)d_in[6];
    const float* bv    = (const float*)d_in[7];
    const float* Woff  = (const float*)d_in[8];
    const float* boff  = (const float*)d_in[9];
    const float* Wa    = (const float*)d_in[10];
    const float* ba    = (const float*)d_in[11];
    const float* Wo    = (const float*)d_in[12];
    const float* bo    = (const float*)d_in[13];

    float *qoab, *kvb, *ab, *wqoa, *wkv, *wot, *bqoa, *bkv;
    cudaGetSymbolAddress((void**)&qoab, g_qoa);
    cudaGetSymbolAddress((void**)&kvb,  g_kv);
    cudaGetSymbolAddress((void**)&ab,   g_attn);
    cudaGetSymbolAddress((void**)&wqoa, g_Wqoa);
    cudaGetSymbolAddress((void**)&wkv,  g_Wkv);
    cudaGetSymbolAddress((void**)&wot,  g_Wo_t);
    cudaGetSymbolAddress((void**)&bqoa, g_bqoa);
    cudaGetSymbolAddress((void**)&bkv,  g_bkv);

    cudaFuncSetAttribute(gemm_tf32<true>,
                         cudaFuncAttributeMaxDynamicSharedMemorySize, DYN_SMEM);
    cudaFuncSetAttribute(gemm_tf32<false>,
                         cudaFuncAttributeMaxDynamicSharedMemorySize, DYN_SMEM);

    // Fused + tf32-converted weights (convcpy), fused biases (memcpy)
    const int S = DM * DM;            // 262144
    convcpy<<<(S + 255) / 256, 256>>>(wqoa,            Wq,   S);
    convcpy<<<(32*DM + 255) / 256, 256>>>(wqoa + S,        Woff, 32 * DM);
    convcpy<<<(32*DM + 255) / 256, 256>>>(wqoa + S + 32*DM, Wa,  32 * DM);
    convcpy<<<(S + 255) / 256, 256>>>(wkv,             Wk,   S);
    convcpy<<<(S + 255) / 256, 256>>>(wkv + S,         Wv,   S);
    convcpy<<<(S + 255) / 256, 256>>>(wot,             Wo,   S);

    cudaMemcpyAsync(bqoa,       bq,   DM * 4, cudaMemcpyDeviceToDevice);
    cudaMemcpyAsync(bqoa + 512, boff, 32 * 4, cudaMemcpyDeviceToDevice);
    cudaMemcpyAsync(bqoa + 544, ba,   32 * 4, cudaMemcpyDeviceToDevice);
    cudaMemcpyAsync(bkv,        bk,   DM * 4, cudaMemcpyDeviceToDevice);
    cudaMemcpyAsync(bkv + 512,  bv,   DM * 4, cudaMemcpyDeviceToDevice);

    dim3 blk(256);
    dim3 gQoa((NQOA + BN - 1) / BN, MTOT / BM);  // (5, 128)
    dim3 gKv (NKV / BN,            MTOT / BM);   // (8, 128)
    dim3 gOut(DM / BN,             MTOT / BM);   // (4, 128)

    gemm_tf32<true ><<<gQoa, blk, DYN_SMEM>>>(q_in,  wqoa, bqoa, qoab, NQOA);
    gemm_tf32<true ><<<gKv,  blk, DYN_SMEM>>>(kv_in, wkv,  bkv,  kvb,  NKV);

    attn_kernel<<<(MTOT * H_) / 8, 256>>>(qoab, kvb, ab);

    gemm_tf32<false><<<gOut, blk, DYN_SMEM>>>(ab, wot, bo, (float*)d_out, DM);
}

// round 12
// speedup vs baseline: 3.8695x; 1.0656x over previous
#include <cuda_runtime.h>
#include <math.h>
#include <stdint.h>

// Problem constants (fixed by setup_inputs)
#define B_  4
#define L_  4096
#define DM  512
#define H_  8
#define P_  4
#define D_  64
#define MTOT (B_*L_)   // 16384

#define NQOA 576       // Wq | Woff | Wa fused output cols
#define NKV  1024      // Wk | Wv fused output cols

// GEMM tiling: CTA 128x128x32, 128 threads = 4 warps, warp tile 64x64
#define BM 128
#define BN 128
#define BK 32
#define NSTAGES 3
#define KTILES (DM/BK)          // 16
#define LDSA (BK + 4)           // 36 floats per smem row (conflict-free)
#define ATILE (BM * LDSA)
#define BTILE (BN * LDSA)
#define STAGEF (ATILE + BTILE)  // 9216 floats
#define DYN_SMEM (NSTAGES * STAGEF * 4)  // 110592 B -> 2 CTAs/SM

// Scratch (no cudaMalloc allowed)
__device__ float g_qoa [(size_t)MTOT*NQOA];
__device__ float g_kv  [(size_t)MTOT*NKV];
__device__ float g_attn[(size_t)MTOT*DM];
__device__ float g_Wqoa[640*DM];
__device__ float g_Wkv [NKV*DM];
__device__ float g_Wo_t[DM*DM];
__device__ float g_bqoa[640];
__device__ float g_bkv [NKV];

// ---------------------------------------------------------------------------
__device__ __forceinline__ uint32_t smem_u32(const void* p) {
    uint32_t a;
    asm("{ .reg .u64 t; cvta.to.shared.u64 t, %1; cvt.u32.u64 %0, t; }"
        : "=r"(a) : "l"(p));
    return a;
}

__device__ __forceinline__ void cp16(uint32_t dst, const float* src, uint32_t sz) {
    asm volatile("cp.async.cg.shared.global [%0], [%1], 16, %2;\n"
                 :: "r"(dst), "l"(src), "r"(sz));
}

// round-to-nearest fp32 -> tf32 (zero-mean rounding error)
__device__ __forceinline__ uint32_t f2tf(float x) {
    uint32_t r;
    asm("cvt.rna.tf32.f32 %0, %1;" : "=r"(r) : "f"(x));
    return r;
}

__device__ __forceinline__ void mma_tf32(float* c, const uint32_t* a, const uint32_t* b) {
    asm volatile(
        "mma.sync.aligned.m16n8k8.row.col.f32.tf32.tf32.f32 "
        "{%0,%1,%2,%3}, {%4,%5,%6,%7}, {%8,%9}, {%0,%1,%2,%3};"
        : "+f"(c[0]), "+f"(c[1]), "+f"(c[2]), "+f"(c[3])
        : "r"(a[0]), "r"(a[1]), "r"(a[2]), "r"(a[3]), "r"(b[0]), "r"(b[1]));
}

// ---------------------------------------------------------------------------
// Fused prologue: tf32-convert all weights into fused buffers + copy biases.
// Flat float4 index over virtual concat:
//   [Wq 65536][Woff 4096][Wa 4096][Wk 65536][Wv 65536][Wo 65536][biases 400]
// ---------------------------------------------------------------------------
#define PRE_TOTAL 270736
__device__ __forceinline__ float4 cv4(float4 v) {
    return make_float4(__uint_as_float(f2tf(v.x)), __uint_as_float(f2tf(v.y)),
                       __uint_as_float(f2tf(v.z)), __uint_as_float(f2tf(v.w)));
}
__global__ __launch_bounds__(256) void prep(
    float* __restrict__ wqoa, float* __restrict__ wkv, float* __restrict__ wot,
    float* __restrict__ bqoa, float* __restrict__ bkv,
    const float* __restrict__ Wq, const float* __restrict__ Woff,
    const float* __restrict__ Wa, const float* __restrict__ Wk,
    const float* __restrict__ Wv, const float* __restrict__ Wo,
    const float* __restrict__ bq, const float* __restrict__ boff,
    const float* __restrict__ ba, const float* __restrict__ bk,
    const float* __restrict__ bv)
{
    int i = blockIdx.x * blockDim.x + threadIdx.x;
    if (i >= PRE_TOTAL) return;
    if (i < 270336) {
        const float* src; float* dst; int d;
        if      (i <  65536) { src = Wq;   dst = wqoa;                d = i; }
        else if (i <  69632) { src = Woff; dst = wqoa + 65536*4;      d = i - 65536; }
        else if (i <  73728) { src = Wa;   dst = wqoa + 69632*4;      d = i - 69632; }
        else if (i < 139264) { src = Wk;   dst = wkv;                 d = i - 73728; }
        else if (i < 204800) { src = Wv;   dst = wkv + 65536*4;       d = i - 139264; }
        else                 { src = Wo;   dst = wot;                 d = i - 204800; }
        ((float4*)dst)[d] = cv4(((const float4*)src)[d]);
    } else {
        int j = i - 270336;   // bias float4 index, raw copy
        const float* src; float* dst; int d;
        if      (j < 128) { src = bq;   dst = bqoa;            d = j; }
        else if (j < 136) { src = boff; dst = bqoa + 512;      d = j - 128; }
        else if (j < 144) { src = ba;   dst = bqoa + 544;      d = j - 136; }
        else if (j < 272) { src = bk;   dst = bkv;             d = j - 144; }
        else              { src = bv;   dst = bkv + 512;       d = j - 272; }
        ((float4*)dst)[d] = ((const float4*)src)[d];
    }
}

// ---------------------------------------------------------------------------
// C[M,N] = A[M,512] @ W[N,512]^T + bias[N] via mma.sync tf32.
// CTA: 128x128 tile, 128 threads = 4 warps (2m x 2n), warp tile 64x64.
// cp.async 3-stage pipeline, 2 CTAs/SM. W pre-converted tf32 bits.
// ---------------------------------------------------------------------------
template<bool CONVA>
__global__ __launch_bounds__(128, 2) void gemm_tf32(
    const float* __restrict__ A, const float* __restrict__ W,
    const float* __restrict__ bias, float* __restrict__ C, int N)
{
    extern __shared__ float sm[];

    const int tid    = threadIdx.x;
    const int lane   = tid & 31;
    const int wid    = tid >> 5;       // 0..3
    const int warp_m = wid >> 1;       // 0..1 -> *64
    const int warp_n = wid & 1;        // 0..1 -> *64
    const int m0     = blockIdx.y * BM;
    const int n0     = blockIdx.x * BN;
    const int r      = lane >> 2;      // 0..7
    const int c      = lane & 3;       // 0..3

    float acc[4][8][4];
#pragma unroll
    for (int i = 0; i < 4; i++)
#pragma unroll
        for (int j = 0; j < 8; j++)
#pragma unroll
            for (int q = 0; q < 4; q++) acc[i][j][q] = 0.f;

    const uint32_t smb = smem_u32(sm);

    auto load_tile = [&](int t) {
        const int s = t % NSTAGES;
        const uint32_t sa = smb + (uint32_t)(s * STAGEF) * 4u;
        const uint32_t sb = sa + (uint32_t)ATILE * 4u;
        const int k0 = t * BK;
#pragma unroll
        for (int i = 0; i < 8; i++) {
            const int idx = tid + i * 128;       // 0..1023
            const int row = idx >> 3;
            const int kc  = (idx & 7) * 4;
            cp16(sa + (uint32_t)(row * LDSA + kc) * 4u,
                 A + (size_t)(m0 + row) * DM + k0 + kc, 16u);
            const int wr = n0 + row;
            const float* bsrc = W + (size_t)(wr < N ? wr : 0) * DM + k0 + kc;
            cp16(sb + (uint32_t)(row * LDSA + kc) * 4u, bsrc, wr < N ? 16u : 0u);
        }
        asm volatile("cp.async.commit_group;\n");
    };

#pragma unroll
    for (int t = 0; t < NSTAGES - 1; t++) load_tile(t);

    for (int t = 0; t < KTILES; t++) {
        asm volatile("cp.async.wait_group %0;\n" :: "n"(NSTAGES - 2));
        __syncthreads();

        if (t + NSTAGES - 1 < KTILES) load_tile(t + NSTAGES - 1);
        else asm volatile("cp.async.commit_group;\n");

        const float*    sA = sm + (t % NSTAGES) * STAGEF;
        const uint32_t* sB = (const uint32_t*)(sA + ATILE);
        const float*    aBase = sA + (warp_m * 64 + r) * LDSA + c;
        const uint32_t* bBase = sB + (warp_n * 64 + r) * LDSA + c;

#pragma unroll
        for (int ks = 0; ks < 4; ks++) {
            const int k0 = ks * 8;
            uint32_t af[4][4];
#pragma unroll
            for (int mf = 0; mf < 4; mf++) {
                if (CONVA) {
                    af[mf][0] = f2tf(aBase[(mf * 16    ) * LDSA + k0    ]);
                    af[mf][1] = f2tf(aBase[(mf * 16 + 8) * LDSA + k0    ]);
                    af[mf][2] = f2tf(aBase[(mf * 16    ) * LDSA + k0 + 4]);
                    af[mf][3] = f2tf(aBase[(mf * 16 + 8) * LDSA + k0 + 4]);
                } else {
                    const uint32_t* aU = (const uint32_t*)aBase;
                    af[mf][0] = aU[(mf * 16    ) * LDSA + k0    ];
                    af[mf][1] = aU[(mf * 16 + 8) * LDSA + k0    ];
                    af[mf][2] = aU[(mf * 16    ) * LDSA + k0 + 4];
                    af[mf][3] = aU[(mf * 16 + 8) * LDSA + k0 + 4];
                }
            }
#pragma unroll
            for (int nf = 0; nf < 8; nf++) {
                uint32_t bf[2];
                bf[0] = bBase[nf * 8 * LDSA + k0    ];
                bf[1] = bBase[nf * 8 * LDSA + k0 + 4];
#pragma unroll
                for (int mf = 0; mf < 4; mf++)
                    mma_tf32(acc[mf][nf], af[mf], bf);
            }
        }
        // no bottom sync: top sync of next iter protects stage reuse
    }

    // epilogue: bias + store
#pragma unroll
    for (int mf = 0; mf < 4; mf++) {
        const int row0 = m0 + warp_m * 64 + mf * 16 + r;
#pragma unroll
        for (int nf = 0; nf < 8; nf++) {
            const int col = n0 + warp_n * 64 + nf * 8 + c * 2;
            if (col < N) {
                const float bx = bias[col], by = bias[col + 1];
                float2 o0 = make_float2(acc[mf][nf][0] + bx, acc[mf][nf][1] + by);
                float2 o1 = make_float2(acc[mf][nf][2] + bx, acc[mf][nf][3] + by);
                *(float2*)(C + (size_t)row0 * N + col)       = o0;
                *(float2*)(C + (size_t)(row0 + 8) * N + col) = o1;
            }
        }
    }
}

// ---------------------------------------------------------------------------
// Deformable attention. One warp per (b,l,h); lane owns a float2 of D=64.
// qoa: [M, 576] = q | offsets | logits.  kv: [M, 1024] = k | v.
// Output written tf32-rounded (feeds Wo GEMM with CONVA=false).
// ---------------------------------------------------------------------------
__global__ __launch_bounds__(256) void attn_kernel(
    const float* __restrict__ qoa, const float* __restrict__ kv,
    float* __restrict__ out)
{
    const int gw   = (blockIdx.x * blockDim.x + threadIdx.x) >> 5;
    const int lane = threadIdx.x & 31;
    const int h    = gw & (H_ - 1);
    const int bl   = gw >> 3;          // b*L + l
    const int l    = bl & (L_ - 1);
    const int brow = bl - l;           // b*L

    const float2 qd = *(const float2*)(qoa + (size_t)bl * NQOA + h * D_ + 2 * lane);
    const float* op = qoa + (size_t)bl * NQOA + 512 + h * P_;
    const float* lp = op + 32;

    float  dots[P_];
    float2 vs[P_];

#pragma unroll
    for (int p = 0; p < P_; p++) {
        float pos = (float)l + op[p];
        pos = fminf(fmaxf(pos, 0.f), (float)(L_ - 1));
        float fi = floorf(pos);
        int   i0 = (int)fi;
        int   i1 = min(i0 + 1, L_ - 1);
        float w  = pos - fi;

        const float* row0 = kv + (size_t)(brow + i0) * NKV + h * D_ + 2 * lane;
        const float* row1 = kv + (size_t)(brow + i1) * NKV + h * D_ + 2 * lane;
        float2 k0 = *(const float2*)(row0);
        float2 k1 = *(const float2*)(row1);
        float2 v0 = *(const float2*)(row0 + 512);
        float2 v1 = *(const float2*)(row1 + 512);

        float2 ks;
        ks.x = (1.f - w) * k0.x + w * k1.x;
        ks.y = (1.f - w) * k0.y + w * k1.y;
        vs[p].x = (1.f - w) * v0.x + w * v1.x;
        vs[p].y = (1.f - w) * v0.y + w * v1.y;

        float d = qd.x * ks.x + qd.y * ks.y;
#pragma unroll
        for (int s = 16; s > 0; s >>= 1)
            d += __shfl_xor_sync(0xffffffffu, d, s);
        dots[p] = d;
    }

    float s0 = dots[0] * 0.125f + lp[0];
    float s1 = dots[1] * 0.125f + lp[1];
    float s2 = dots[2] * 0.125f + lp[2];
    float s3 = dots[3] * 0.125f + lp[3];
    float m  = fmaxf(fmaxf(s0, s1), fmaxf(s2, s3));
    float e0 = expf(s0 - m), e1 = expf(s1 - m);
    float e2 = expf(s2 - m), e3 = expf(s3 - m);
    float inv = 1.f / (e0 + e1 + e2 + e3);

    float ox = (e0 * vs[0].x + e1 * vs[1].x + e2 * vs[2].x + e3 * vs[3].x) * inv;
    float oy = (e0 * vs[0].y + e1 * vs[1].y + e2 * vs[2].y + e3 * vs[3].y) * inv;
    float2 o = make_float2(__uint_as_float(f2tf(ox)), __uint_as_float(f2tf(oy)));
    *(float2*)(out + (size_t)bl * DM + h * D_ + 2 * lane) = o;
}

// ---------------------------------------------------------------------------
extern "C" void kernel_launch(void* const* d_in, const int* in_sizes, int n_in,
                              void* d_out, int out_size)
{
    const float* q_in  = (const float*)d_in[0];
    const float* kv_in = (const float*)d_in[1];
    const float* Wq    = (const float*)d_in[2];
    const float* bq    = (const float*)d_in[3];
    const float* Wk    = (const float*)d_in[4];
    const float* bk    = (const float*)d_in[5];
    const float* Wv    = (const float*)d_in[6];
    const float* bv    = (const float*)d_in[7];
    const float* Woff  = (const float*)d_in[8];
    const float* boff  = (const float*)d_in[9];
    const float* Wa    = (const float*)d_in[10];
    const float* ba    = (const float*)d_in[11];
    const float* Wo    = (const float*)d_in[12];
    const float* bo    = (const float*)d_in[13];

    float *qoab, *kvb, *ab, *wqoa, *wkv, *wot, *bqoa, *bkv;
    cudaGetSymbolAddress((void**)&qoab, g_qoa);
    cudaGetSymbolAddress((void**)&kvb,  g_kv);
    cudaGetSymbolAddress((void**)&ab,   g_attn);
    cudaGetSymbolAddress((void**)&wqoa, g_Wqoa);
    cudaGetSymbolAddress((void**)&wkv,  g_Wkv);
    cudaGetSymbolAddress((void**)&wot,  g_Wo_t);
    cudaGetSymbolAddress((void**)&bqoa, g_bqoa);
    cudaGetSymbolAddress((void**)&bkv,  g_bkv);

    cudaFuncSetAttribute(gemm_tf32<true>,
                         cudaFuncAttributeMaxDynamicSharedMemorySize, DYN_SMEM);
    cudaFuncSetAttribute(gemm_tf32<false>,
                         cudaFuncAttributeMaxDynamicSharedMemorySize, DYN_SMEM);

    // One fused prologue launch: all weight conversions + bias copies
    prep<<<(PRE_TOTAL + 255) / 256, 256>>>(
        wqoa, wkv, wot, bqoa, bkv,
        Wq, Woff, Wa, Wk, Wv, Wo, bq, boff, ba, bk, bv);

    dim3 blk(128);
    dim3 gQoa((NQOA + BN - 1) / BN, MTOT / BM);  // (5, 128)
    dim3 gKv (NKV / BN,            MTOT / BM);   // (8, 128)
    dim3 gOut(DM / BN,             MTOT / BM);   // (4, 128)

    gemm_tf32<true ><<<gQoa, blk, DYN_SMEM>>>(q_in,  wqoa, bqoa, qoab, NQOA);
    gemm_tf32<true ><<<gKv,  blk, DYN_SMEM>>>(kv_in, wkv,  bkv,  kvb,  NKV);

    attn_kernel<<<(MTOT * H_) / 8, 256>>>(qoab, kvb, ab);

    gemm_tf32<false><<<gOut, blk, DYN_SMEM>>>(ab, wot, bo, (float*)d_out, DM);
}

// round 14
// speedup vs baseline: 4.0151x; 1.0376x over previous
#include <cuda_runtime.h>
#include <math.h>
#include <stdint.h>

// Problem constants (fixed by setup_inputs)
#define B_  4
#define L_  4096
#define DM  512
#define H_  8
#define P_  4
#define D_  64
#define MTOT (B_*L_)   // 16384

#define NQOA 576       // Wq | Woff | Wa fused output cols
#define NKV  1024      // Wk | Wv fused output cols

// GEMM tiling: CTA 128x128x32, 128 threads = 4 warps, warp tile 64x64
#define BM 128
#define BN 128
#define BK 32
#define NSTAGES 3
#define KTILES (DM/BK)          // 16
#define LDSA (BK + 4)           // 36 floats per smem row (conflict-free)
#define ATILE (BM * LDSA)
#define BTILE (BN * LDSA)
#define STAGEF (ATILE + BTILE)  // 9216 floats
#define DYN_SMEM (NSTAGES * STAGEF * 4)  // 110592 B -> 2 CTAs/SM

// Scratch (no cudaMalloc allowed)
__device__ float g_qoa [(size_t)MTOT*NQOA];
__device__ float g_kv  [(size_t)MTOT*NKV];
__device__ float g_attn[(size_t)MTOT*DM];
__device__ float g_Wqoa[640*DM];
__device__ float g_Wkv [NKV*DM];
__device__ float g_Wo_t[DM*DM];
__device__ float g_bqoa[640];
__device__ float g_bkv [NKV];

// ---------------------------------------------------------------------------
__device__ __forceinline__ uint32_t smem_u32(const void* p) {
    uint32_t a;
    asm("{ .reg .u64 t; cvta.to.shared.u64 t, %1; cvt.u32.u64 %0, t; }"
        : "=r"(a) : "l"(p));
    return a;
}

__device__ __forceinline__ void cp16(uint32_t dst, const float* src, uint32_t sz) {
    asm volatile("cp.async.cg.shared.global [%0], [%1], 16, %2;\n"
                 :: "r"(dst), "l"(src), "r"(sz));
}

// round-to-nearest fp32 -> tf32 (zero-mean rounding error)
__device__ __forceinline__ uint32_t f2tf(float x) {
    uint32_t r;
    asm("cvt.rna.tf32.f32 %0, %1;" : "=r"(r) : "f"(x));
    return r;
}

__device__ __forceinline__ void mma_tf32(float* c, const uint32_t* a, const uint32_t* b) {
    asm volatile(
        "mma.sync.aligned.m16n8k8.row.col.f32.tf32.tf32.f32 "
        "{%0,%1,%2,%3}, {%4,%5,%6,%7}, {%8,%9}, {%0,%1,%2,%3};"
        : "+f"(c[0]), "+f"(c[1]), "+f"(c[2]), "+f"(c[3])
        : "r"(a[0]), "r"(a[1]), "r"(a[2]), "r"(a[3]), "r"(b[0]), "r"(b[1]));
}

// ---------------------------------------------------------------------------
// Fused prologue: tf32-convert all weights into fused buffers + copy biases.
// ---------------------------------------------------------------------------
#define PRE_TOTAL 270736
__device__ __forceinline__ float4 cv4(float4 v) {
    return make_float4(__uint_as_float(f2tf(v.x)), __uint_as_float(f2tf(v.y)),
                       __uint_as_float(f2tf(v.z)), __uint_as_float(f2tf(v.w)));
}
__global__ __launch_bounds__(256) void prep(
    float* __restrict__ wqoa, float* __restrict__ wkv, float* __restrict__ wot,
    float* __restrict__ bqoa, float* __restrict__ bkv,
    const float* __restrict__ Wq, const float* __restrict__ Woff,
    const float* __restrict__ Wa, const float* __restrict__ Wk,
    const float* __restrict__ Wv, const float* __restrict__ Wo,
    const float* __restrict__ bq, const float* __restrict__ boff,
    const float* __restrict__ ba, const float* __restrict__ bk,
    const float* __restrict__ bv)
{
    int i = blockIdx.x * blockDim.x + threadIdx.x;
    if (i >= PRE_TOTAL) return;
    if (i < 270336) {
        const float* src; float* dst; int d;
        if      (i <  65536) { src = Wq;   dst = wqoa;                d = i; }
        else if (i <  69632) { src = Woff; dst = wqoa + 65536*4;      d = i - 65536; }
        else if (i <  73728) { src = Wa;   dst = wqoa + 69632*4;      d = i - 69632; }
        else if (i < 139264) { src = Wk;   dst = wkv;                 d = i - 73728; }
        else if (i < 204800) { src = Wv;   dst = wkv + 65536*4;       d = i - 139264; }
        else                 { src = Wo;   dst = wot;                 d = i - 204800; }
        ((float4*)dst)[d] = cv4(((const float4*)src)[d]);
    } else {
        int j = i - 270336;
        const float* src; float* dst; int d;
        if      (j < 128) { src = bq;   dst = bqoa;            d = j; }
        else if (j < 136) { src = boff; dst = bqoa + 512;      d = j - 128; }
        else if (j < 144) { src = ba;   dst = bqoa + 544;      d = j - 136; }
        else if (j < 272) { src = bk;   dst = bkv;             d = j - 144; }
        else              { src = bv;   dst = bkv + 512;       d = j - 272; }
        ((float4*)dst)[d] = ((const float4*)src)[d];
    }
}

// ---------------------------------------------------------------------------
// GEMM body: C[M,N] = A[M,512] @ W[N,512]^T + bias[N] via mma.sync tf32.
// CTA: 128x128 tile, 128 threads = 4 warps (2m x 2n), warp tile 64x64.
// cp.async 3-stage pipeline + register fragment double-buffering.
// ---------------------------------------------------------------------------
template<bool CONVA>
__device__ __forceinline__ void gemm_body(
    const float* __restrict__ A, const float* __restrict__ W,
    const float* __restrict__ bias, float* __restrict__ C,
    int N, int n0, int m0, float* sm)
{
    const int tid    = threadIdx.x;
    const int lane   = tid & 31;
    const int wid    = tid >> 5;
    const int warp_m = wid >> 1;
    const int warp_n = wid & 1;
    const int r      = lane >> 2;
    const int c      = lane & 3;

    float acc[4][8][4];
#pragma unroll
    for (int i = 0; i < 4; i++)
#pragma unroll
        for (int j = 0; j < 8; j++)
#pragma unroll
            for (int q = 0; q < 4; q++) acc[i][j][q] = 0.f;

    const uint32_t smb = smem_u32(sm);

    auto load_tile = [&](int t) {
        const int s = t % NSTAGES;
        const uint32_t sa = smb + (uint32_t)(s * STAGEF) * 4u;
        const uint32_t sb = sa + (uint32_t)ATILE * 4u;
        const int k0 = t * BK;
#pragma unroll
        for (int i = 0; i < 8; i++) {
            const int idx = tid + i * 128;
            const int row = idx >> 3;
            const int kc  = (idx & 7) * 4;
            cp16(sa + (uint32_t)(row * LDSA + kc) * 4u,
                 A + (size_t)(m0 + row) * DM + k0 + kc, 16u);
            const int wr = n0 + row;
            const float* bsrc = W + (size_t)(wr < N ? wr : 0) * DM + k0 + kc;
            cp16(sb + (uint32_t)(row * LDSA + kc) * 4u, bsrc, wr < N ? 16u : 0u);
        }
        asm volatile("cp.async.commit_group;\n");
    };

#pragma unroll
    for (int t = 0; t < NSTAGES - 1; t++) load_tile(t);

    for (int t = 0; t < KTILES; t++) {
        asm volatile("cp.async.wait_group %0;\n" :: "n"(NSTAGES - 2));
        __syncthreads();

        if (t + NSTAGES - 1 < KTILES) load_tile(t + NSTAGES - 1);
        else asm volatile("cp.async.commit_group;\n");

        const float*    sA = sm + (t % NSTAGES) * STAGEF;
        const uint32_t* sB = (const uint32_t*)(sA + ATILE);
        const float*    aBase = sA + (warp_m * 64 + r) * LDSA + c;
        const uint32_t* bBase = sB + (warp_n * 64 + r) * LDSA + c;

        auto load_af = [&](uint32_t (&af)[4][4], int k0) {
#pragma unroll
            for (int mf = 0; mf < 4; mf++) {
                if (CONVA) {
                    af[mf][0] = f2tf(aBase[(mf * 16    ) * LDSA + k0    ]);
                    af[mf][1] = f2tf(aBase[(mf * 16 + 8) * LDSA + k0    ]);
                    af[mf][2] = f2tf(aBase[(mf * 16    ) * LDSA + k0 + 4]);
                    af[mf][3] = f2tf(aBase[(mf * 16 + 8) * LDSA + k0 + 4]);
                } else {
                    const uint32_t* aU = (const uint32_t*)aBase;
                    af[mf][0] = aU[(mf * 16    ) * LDSA + k0    ];
                    af[mf][1] = aU[(mf * 16 + 8) * LDSA + k0    ];
                    af[mf][2] = aU[(mf * 16    ) * LDSA + k0 + 4];
                    af[mf][3] = aU[(mf * 16 + 8) * LDSA + k0 + 4];
                }
            }
        };
        auto load_bf = [&](uint32_t (&bf)[8][2], int k0) {
#pragma unroll
            for (int nf = 0; nf < 8; nf++) {
                bf[nf][0] = bBase[nf * 8 * LDSA + k0    ];
                bf[nf][1] = bBase[nf * 8 * LDSA + k0 + 4];
            }
        };

        uint32_t af0[4][4], af1[4][4], bf0[8][2], bf1[8][2];
        load_af(af0, 0);
        load_bf(bf0, 0);

#pragma unroll
        for (int ks = 0; ks < 4; ks++) {
            uint32_t (&afc)[4][4] = (ks & 1) ? af1 : af0;
            uint32_t (&bfc)[8][2] = (ks & 1) ? bf1 : bf0;
            uint32_t (&afn)[4][4] = (ks & 1) ? af0 : af1;
            uint32_t (&bfn)[8][2] = (ks & 1) ? bf0 : bf1;
            if (ks < 3) {                 // prefetch next ks fragments
                load_af(afn, (ks + 1) * 8);
                load_bf(bfn, (ks + 1) * 8);
            }
#pragma unroll
            for (int nf = 0; nf < 8; nf++)
#pragma unroll
                for (int mf = 0; mf < 4; mf++)
                    mma_tf32(acc[mf][nf], afc[mf], bfc[nf]);
        }
        // no bottom sync: top sync of next iter protects stage reuse
    }

    // epilogue: bias + store
#pragma unroll
    for (int mf = 0; mf < 4; mf++) {
        const int row0 = m0 + warp_m * 64 + mf * 16 + r;
#pragma unroll
        for (int nf = 0; nf < 8; nf++) {
            const int col = n0 + warp_n * 64 + nf * 8 + c * 2;
            if (col < N) {
                const float bx = bias[col], by = bias[col + 1];
                float2 o0 = make_float2(acc[mf][nf][0] + bx, acc[mf][nf][1] + by);
                float2 o1 = make_float2(acc[mf][nf][2] + bx, acc[mf][nf][3] + by);
                *(float2*)(C + (size_t)row0 * N + col)       = o0;
                *(float2*)(C + (size_t)(row0 + 8) * N + col) = o1;
            }
        }
    }
}

// Fused launch: blockIdx.x < 5 -> qoa GEMM (A=q_in), else kv GEMM (A=kv_in)
__global__ __launch_bounds__(128, 2) void gemm_dual(
    const float* __restrict__ Aq, const float* __restrict__ Akv,
    const float* __restrict__ Wqoa_, const float* __restrict__ Wkv_,
    const float* __restrict__ bqoa_, const float* __restrict__ bkv_,
    float* __restrict__ Cqoa, float* __restrict__ Ckv)
{
    extern __shared__ float sm[];
    const int x  = blockIdx.x;
    const int m0 = blockIdx.y * BM;
    if (x < 5) {
        gemm_body<true>(Aq, Wqoa_, bqoa_, Cqoa, NQOA, x * BN, m0, sm);
    } else {
        gemm_body<true>(Akv, Wkv_, bkv_, Ckv, NKV, (x - 5) * BN, m0, sm);
    }
}

__global__ __launch_bounds__(128, 2) void gemm_out(
    const float* __restrict__ A, const float* __restrict__ W,
    const float* __restrict__ bias, float* __restrict__ C)
{
    extern __shared__ float sm[];
    gemm_body<false>(A, W, bias, C, DM, blockIdx.x * BN, blockIdx.y * BM, sm);
}

// ---------------------------------------------------------------------------
// Deformable attention. One warp per (b,l,h); lane owns a float2 of D=64.
// qoa: [M, 576] = q | offsets | logits.  kv: [M, 1024] = k | v.
// Output written tf32-rounded (feeds Wo GEMM with CONVA=false).
// ---------------------------------------------------------------------------
__global__ __launch_bounds__(256) void attn_kernel(
    const float* __restrict__ qoa, const float* __restrict__ kv,
    float* __restrict__ out)
{
    const int gw   = (blockIdx.x * blockDim.x + threadIdx.x) >> 5;
    const int lane = threadIdx.x & 31;
    const int h    = gw & (H_ - 1);
    const int bl   = gw >> 3;          // b*L + l
    const int l    = bl & (L_ - 1);
    const int brow = bl - l;           // b*L

    const float2 qd = *(const float2*)(qoa + (size_t)bl * NQOA + h * D_ + 2 * lane);
    const float* op = qoa + (size_t)bl * NQOA + 512 + h * P_;
    const float* lp = op + 32;

    float  dots[P_];
    float2 vs[P_];

#pragma unroll
    for (int p = 0; p < P_; p++) {
        float pos = (float)l + op[p];
        pos = fminf(fmaxf(pos, 0.f), (float)(L_ - 1));
        float fi = floorf(pos);
        int   i0 = (int)fi;
        int   i1 = min(i0 + 1, L_ - 1);
        float w  = pos - fi;

        const float* row0 = kv + (size_t)(brow + i0) * NKV + h * D_ + 2 * lane;
        const float* row1 = kv + (size_t)(brow + i1) * NKV + h * D_ + 2 * lane;
        float2 k0 = *(const float2*)(row0);
        float2 k1 = *(const float2*)(row1);
        float2 v0 = *(const float2*)(row0 + 512);
        float2 v1 = *(const float2*)(row1 + 512);

        float2 ks;
        ks.x = (1.f - w) * k0.x + w * k1.x;
        ks.y = (1.f - w) * k0.y + w * k1.y;
        vs[p].x = (1.f - w) * v0.x + w * v1.x;
        vs[p].y = (1.f - w) * v0.y + w * v1.y;

        float d = qd.x * ks.x + qd.y * ks.y;
#pragma unroll
        for (int s = 16; s > 0; s >>= 1)
            d += __shfl_xor_sync(0xffffffffu, d, s);
        dots[p] = d;
    }

    float s0 = dots[0] * 0.125f + lp[0];
    float s1 = dots[1] * 0.125f + lp[1];
    float s2 = dots[2] * 0.125f + lp[2];
    float s3 = dots[3] * 0.125f + lp[3];
    float m  = fmaxf(fmaxf(s0, s1), fmaxf(s2, s3));
    float e0 = expf(s0 - m), e1 = expf(s1 - m);
    float e2 = expf(s2 - m), e3 = expf(s3 - m);
    float inv = 1.f / (e0 + e1 + e2 + e3);

    float ox = (e0 * vs[0].x + e1 * vs[1].x + e2 * vs[2].x + e3 * vs[3].x) * inv;
    float oy = (e0 * vs[0].y + e1 * vs[1].y + e2 * vs[2].y + e3 * vs[3].y) * inv;
    float2 o = make_float2(__uint_as_float(f2tf(ox)), __uint_as_float(f2tf(oy)));
    *(float2*)(out + (size_t)bl * DM + h * D_ + 2 * lane) = o;
}

// ---------------------------------------------------------------------------
extern "C" void kernel_launch(void* const* d_in, const int* in_sizes, int n_in,
                              void* d_out, int out_size)
{
    const float* q_in  = (const float*)d_in[0];
    const float* kv_in = (const float*)d_in[1];
    const float* Wq    = (const float*)d_in[2];
    const float* bq    = (const float*)d_in[3];
    const float* Wk    = (const float*)d_in[4];
    const float* bk    = (const float*)d_in[5];
    const float* Wv    = (const float*)d_in[6];
    const float* bv    = (const float*)d_in[7];
    const float* Woff  = (const float*)d_in[8];
    const float* boff  = (const float*)d_in[9];
    const float* Wa    = (const float*)d_in[10];
    const float* ba    = (const float*)d_in[11];
    const float* Wo    = (const float*)d_in[12];
    const float* bo    = (const float*)d_in[13];

    float *qoab, *kvb, *ab, *wqoa, *wkv, *wot, *bqoa, *bkv;
    cudaGetSymbolAddress((void**)&qoab, g_qoa);
    cudaGetSymbolAddress((void**)&kvb,  g_kv);
    cudaGetSymbolAddress((void**)&ab,   g_attn);
    cudaGetSymbolAddress((void**)&wqoa, g_Wqoa);
    cudaGetSymbolAddress((void**)&wkv,  g_Wkv);
    cudaGetSymbolAddress((void**)&wot,  g_Wo_t);
    cudaGetSymbolAddress((void**)&bqoa, g_bqoa);
    cudaGetSymbolAddress((void**)&bkv,  g_bkv);

    cudaFuncSetAttribute(gemm_dual,
                         cudaFuncAttributeMaxDynamicSharedMemorySize, DYN_SMEM);
    cudaFuncSetAttribute(gemm_out,
                         cudaFuncAttributeMaxDynamicSharedMemorySize, DYN_SMEM);

    // One fused prologue launch: all weight conversions + bias copies
    prep<<<(PRE_TOTAL + 255) / 256, 256>>>(
        wqoa, wkv, wot, bqoa, bkv,
        Wq, Woff, Wa, Wk, Wv, Wo, bq, boff, ba, bk, bv);

    // Merged projection GEMMs: x<5 -> qoa (N=576), x>=5 -> kv (N=1024)
    dim3 gDual(13, MTOT / BM);
    gemm_dual<<<gDual, 128, DYN_SMEM>>>(q_in, kv_in, wqoa, wkv, bqoa, bkv,
                                        qoab, kvb);

    attn_kernel<<<(MTOT * H_) / 8, 256>>>(qoab, kvb, ab);

    dim3 gOut(DM / BN, MTOT / BM);
    gemm_out<<<gOut, 128, DYN_SMEM>>>(ab, wot, bo, (float*)d_out);
}

// round 16
// speedup vs baseline: 4.1116x; 1.0240x over previous
#include <cuda_runtime.h>
#include <math.h>
#include <stdint.h>

// Problem constants (fixed by setup_inputs)
#define B_  4
#define L_  4096
#define DM  512
#define H_  8
#define P_  4
#define D_  64
#define MTOT (B_*L_)   // 16384

#define NQOA 576       // Wq | Woff | Wa fused output cols
#define NKV  1024      // Wk | Wv fused output cols

// GEMM tiling: CTA 128x128x32, 256 threads = 8 warps (4m x 2n), warp tile 32x64
#define BM 128
#define BN 128
#define BK 32
#define NSTAGES 3
#define KTILES (DM/BK)          // 16
#define LDSA (BK + 4)           // 36 floats per smem row (conflict-free)
#define ATILE (BM * LDSA)
#define BTILE (BN * LDSA)
#define STAGEF (ATILE + BTILE)  // 9216 floats
#define DYN_SMEM (NSTAGES * STAGEF * 4)  // 110592 B -> 2 CTAs/SM

// Scratch (no cudaMalloc allowed)
__device__ float g_qoa [(size_t)MTOT*NQOA];
__device__ float g_kv  [(size_t)MTOT*NKV];
__device__ float g_attn[(size_t)MTOT*DM];
__device__ float g_Wqoa[640*DM];
__device__ float g_Wkv [NKV*DM];
__device__ float g_Wo_t[DM*DM];
__device__ float g_bqoa[640];
__device__ float g_bkv [NKV];

// ---------------------------------------------------------------------------
__device__ __forceinline__ uint32_t smem_u32(const void* p) {
    uint32_t a;
    asm("{ .reg .u64 t; cvta.to.shared.u64 t, %1; cvt.u32.u64 %0, t; }"
        : "=r"(a) : "l"(p));
    return a;
}

__device__ __forceinline__ void cp16(uint32_t dst, const float* src, uint32_t sz) {
    asm volatile("cp.async.cg.shared.global [%0], [%1], 16, %2;\n"
                 :: "r"(dst), "l"(src), "r"(sz));
}

// round-to-nearest fp32 -> tf32 (zero-mean rounding error)
__device__ __forceinline__ uint32_t f2tf(float x) {
    uint32_t r;
    asm("cvt.rna.tf32.f32 %0, %1;" : "=r"(r) : "f"(x));
    return r;
}

__device__ __forceinline__ void mma_tf32(float* c, const uint32_t* a, const uint32_t* b) {
    asm volatile(
        "mma.sync.aligned.m16n8k8.row.col.f32.tf32.tf32.f32 "
        "{%0,%1,%2,%3}, {%4,%5,%6,%7}, {%8,%9}, {%0,%1,%2,%3};"
        : "+f"(c[0]), "+f"(c[1]), "+f"(c[2]), "+f"(c[3])
        : "r"(a[0]), "r"(a[1]), "r"(a[2]), "r"(a[3]), "r"(b[0]), "r"(b[1]));
}

// ---------------------------------------------------------------------------
// Fused prologue: tf32-convert all weights into fused buffers + copy biases.
// ---------------------------------------------------------------------------
#define PRE_TOTAL 270736
__device__ __forceinline__ float4 cv4(float4 v) {
    return make_float4(__uint_as_float(f2tf(v.x)), __uint_as_float(f2tf(v.y)),
                       __uint_as_float(f2tf(v.z)), __uint_as_float(f2tf(v.w)));
}
__global__ __launch_bounds__(256) void prep(
    float* __restrict__ wqoa, float* __restrict__ wkv, float* __restrict__ wot,
    float* __restrict__ bqoa, float* __restrict__ bkv,
    const float* __restrict__ Wq, const float* __restrict__ Woff,
    const float* __restrict__ Wa, const float* __restrict__ Wk,
    const float* __restrict__ Wv, const float* __restrict__ Wo,
    const float* __restrict__ bq, const float* __restrict__ boff,
    const float* __restrict__ ba, const float* __restrict__ bk,
    const float* __restrict__ bv)
{
    int i = blockIdx.x * blockDim.x + threadIdx.x;
    if (i >= PRE_TOTAL) return;
    if (i < 270336) {
        const float* src; float* dst; int d;
        if      (i <  65536) { src = Wq;   dst = wqoa;                d = i; }
        else if (i <  69632) { src = Woff; dst = wqoa + 65536*4;      d = i - 65536; }
        else if (i <  73728) { src = Wa;   dst = wqoa + 69632*4;      d = i - 69632; }
        else if (i < 139264) { src = Wk;   dst = wkv;                 d = i - 73728; }
        else if (i < 204800) { src = Wv;   dst = wkv + 65536*4;       d = i - 139264; }
        else                 { src = Wo;   dst = wot;                 d = i - 204800; }
        ((float4*)dst)[d] = cv4(((const float4*)src)[d]);
    } else {
        int j = i - 270336;
        const float* src; float* dst; int d;
        if      (j < 128) { src = bq;   dst = bqoa;            d = j; }
        else if (j < 136) { src = boff; dst = bqoa + 512;      d = j - 128; }
        else if (j < 144) { src = ba;   dst = bqoa + 544;      d = j - 136; }
        else if (j < 272) { src = bk;   dst = bkv;             d = j - 144; }
        else              { src = bv;   dst = bkv + 512;       d = j - 272; }
        ((float4*)dst)[d] = ((const float4*)src)[d];
    }
}

// ---------------------------------------------------------------------------
// GEMM body: C[M,N] = A[M,512] @ W[N,512]^T + bias[N] via mma.sync tf32.
// CTA: 128x128 tile, 256 threads = 8 warps (4m x 2n), warp tile 32x64.
// cp.async 3-stage pipeline; occupancy (4 warps/SMSP) hides LDS latency.
// ---------------------------------------------------------------------------
template<bool CONVA>
__device__ __forceinline__ void gemm_body(
    const float* __restrict__ A, const float* __restrict__ W,
    const float* __restrict__ bias, float* __restrict__ C,
    int N, int n0, int m0, float* sm)
{
    const int tid    = threadIdx.x;
    const int lane   = tid & 31;
    const int wid    = tid >> 5;       // 0..7
    const int warp_m = wid >> 1;       // 0..3 -> *32
    const int warp_n = wid & 1;        // 0..1 -> *64
    const int r      = lane >> 2;      // 0..7
    const int c      = lane & 3;       // 0..3

    float acc[2][8][4];
#pragma unroll
    for (int i = 0; i < 2; i++)
#pragma unroll
        for (int j = 0; j < 8; j++)
#pragma unroll
            for (int q = 0; q < 4; q++) acc[i][j][q] = 0.f;

    const uint32_t smb = smem_u32(sm);

    auto load_tile = [&](int t) {
        const int s = t % NSTAGES;
        const uint32_t sa = smb + (uint32_t)(s * STAGEF) * 4u;
        const uint32_t sb = sa + (uint32_t)ATILE * 4u;
        const int k0 = t * BK;
#pragma unroll
        for (int i = 0; i < 4; i++) {
            const int idx = tid + i * 256;       // 0..1023
            const int row = idx >> 3;
            const int kc  = (idx & 7) * 4;
            cp16(sa + (uint32_t)(row * LDSA + kc) * 4u,
                 A + (size_t)(m0 + row) * DM + k0 + kc, 16u);
            const int wr = n0 + row;
            const float* bsrc = W + (size_t)(wr < N ? wr : 0) * DM + k0 + kc;
            cp16(sb + (uint32_t)(row * LDSA + kc) * 4u, bsrc, wr < N ? 16u : 0u);
        }
        asm volatile("cp.async.commit_group;\n");
    };

#pragma unroll
    for (int t = 0; t < NSTAGES - 1; t++) load_tile(t);

    for (int t = 0; t < KTILES; t++) {
        asm volatile("cp.async.wait_group %0;\n" :: "n"(NSTAGES - 2));
        __syncthreads();

        if (t + NSTAGES - 1 < KTILES) load_tile(t + NSTAGES - 1);
        else asm volatile("cp.async.commit_group;\n");

        const float*    sA = sm + (t % NSTAGES) * STAGEF;
        const uint32_t* sB = (const uint32_t*)(sA + ATILE);
        const float*    aBase = sA + (warp_m * 32 + r) * LDSA + c;
        const uint32_t* bBase = sB + (warp_n * 64 + r) * LDSA + c;

#pragma unroll
        for (int ks = 0; ks < 4; ks++) {
            const int k0 = ks * 8;
            uint32_t af[2][4];
#pragma unroll
            for (int mf = 0; mf < 2; mf++) {
                if (CONVA) {
                    af[mf][0] = f2tf(aBase[(mf * 16    ) * LDSA + k0    ]);
                    af[mf][1] = f2tf(aBase[(mf * 16 + 8) * LDSA + k0    ]);
                    af[mf][2] = f2tf(aBase[(mf * 16    ) * LDSA + k0 + 4]);
                    af[mf][3] = f2tf(aBase[(mf * 16 + 8) * LDSA + k0 + 4]);
                } else {
                    const uint32_t* aU = (const uint32_t*)aBase;
                    af[mf][0] = aU[(mf * 16    ) * LDSA + k0    ];
                    af[mf][1] = aU[(mf * 16 + 8) * LDSA + k0    ];
                    af[mf][2] = aU[(mf * 16    ) * LDSA + k0 + 4];
                    af[mf][3] = aU[(mf * 16 + 8) * LDSA + k0 + 4];
                }
            }
#pragma unroll
            for (int nf = 0; nf < 8; nf++) {
                uint32_t bf[2];
                bf[0] = bBase[nf * 8 * LDSA + k0    ];
                bf[1] = bBase[nf * 8 * LDSA + k0 + 4];
                mma_tf32(acc[0][nf], af[0], bf);
                mma_tf32(acc[1][nf], af[1], bf);
            }
        }
        // no bottom sync: top sync of next iter protects stage reuse
    }

    // epilogue: bias + store
#pragma unroll
    for (int mf = 0; mf < 2; mf++) {
        const int row0 = m0 + warp_m * 32 + mf * 16 + r;
#pragma unroll
        for (int nf = 0; nf < 8; nf++) {
            const int col = n0 + warp_n * 64 + nf * 8 + c * 2;
            if (col < N) {
                const float bx = bias[col], by = bias[col + 1];
                float2 o0 = make_float2(acc[mf][nf][0] + bx, acc[mf][nf][1] + by);
                float2 o1 = make_float2(acc[mf][nf][2] + bx, acc[mf][nf][3] + by);
                *(float2*)(C + (size_t)row0 * N + col)       = o0;
                *(float2*)(C + (size_t)(row0 + 8) * N + col) = o1;
            }
        }
    }
}

// Fused launch: blockIdx.x < 5 -> qoa GEMM (A=q_in), else kv GEMM (A=kv_in)
__global__ __launch_bounds__(256, 2) void gemm_dual(
    const float* __restrict__ Aq, const float* __restrict__ Akv,
    const float* __restrict__ Wqoa_, const float* __restrict__ Wkv_,
    const float* __restrict__ bqoa_, const float* __restrict__ bkv_,
    float* __restrict__ Cqoa, float* __restrict__ Ckv)
{
    extern __shared__ float sm[];
    const int x  = blockIdx.x;
    const int m0 = blockIdx.y * BM;
    if (x < 5) {
        gemm_body<true>(Aq, Wqoa_, bqoa_, Cqoa, NQOA, x * BN, m0, sm);
    } else {
        gemm_body<true>(Akv, Wkv_, bkv_, Ckv, NKV, (x - 5) * BN, m0, sm);
    }
}

__global__ __launch_bounds__(256, 2) void gemm_out(
    const float* __restrict__ A, const float* __restrict__ W,
    const float* __restrict__ bias, float* __restrict__ C)
{
    extern __shared__ float sm[];
    gemm_body<false>(A, W, bias, C, DM, blockIdx.x * BN, blockIdx.y * BM, sm);
}

// ---------------------------------------------------------------------------
// Deformable attention. One warp per (b,l,h); lane owns a float2 of D=64.
// qoa: [M, 576] = q | offsets | logits.  kv: [M, 1024] = k | v.
// Output written tf32-rounded (feeds Wo GEMM with CONVA=false).
// ---------------------------------------------------------------------------
__global__ __launch_bounds__(256) void attn_kernel(
    const float* __restrict__ qoa, const float* __restrict__ kv,
    float* __restrict__ out)
{
    const int gw   = (blockIdx.x * blockDim.x + threadIdx.x) >> 5;
    const int lane = threadIdx.x & 31;
    const int h    = gw & (H_ - 1);
    const int bl   = gw >> 3;          // b*L + l
    const int l    = bl & (L_ - 1);
    const int brow = bl - l;           // b*L

    const float2 qd = *(const float2*)(qoa + (size_t)bl * NQOA + h * D_ + 2 * lane);
    const float* op = qoa + (size_t)bl * NQOA + 512 + h * P_;
    const float* lp = op + 32;

    float  dots[P_];
    float2 vs[P_];

#pragma unroll
    for (int p = 0; p < P_; p++) {
        float pos = (float)l + op[p];
        pos = fminf(fmaxf(pos, 0.f), (float)(L_ - 1));
        float fi = floorf(pos);
        int   i0 = (int)fi;
        int   i1 = min(i0 + 1, L_ - 1);
        float w  = pos - fi;

        const float* row0 = kv + (size_t)(brow + i0) * NKV + h * D_ + 2 * lane;
        const float* row1 = kv + (size_t)(brow + i1) * NKV + h * D_ + 2 * lane;
        float2 k0 = *(const float2*)(row0);
        float2 k1 = *(const float2*)(row1);
        float2 v0 = *(const float2*)(row0 + 512);
        float2 v1 = *(const float2*)(row1 + 512);

        float2 ks;
        ks.x = (1.f - w) * k0.x + w * k1.x;
        ks.y = (1.f - w) * k0.y + w * k1.y;
        vs[p].x = (1.f - w) * v0.x + w * v1.x;
        vs[p].y = (1.f - w) * v0.y + w * v1.y;

        float d = qd.x * ks.x + qd.y * ks.y;
#pragma unroll
        for (int s = 16; s > 0; s >>= 1)
            d += __shfl_xor_sync(0xffffffffu, d, s);
        dots[p] = d;
    }

    float s0 = dots[0] * 0.125f + lp[0];
    float s1 = dots[1] * 0.125f + lp[1];
    float s2 = dots[2] * 0.125f + lp[2];
    float s3 = dots[3] * 0.125f + lp[3];
    float m  = fmaxf(fmaxf(s0, s1), fmaxf(s2, s3));
    float e0 = expf(s0 - m), e1 = expf(s1 - m);
    float e2 = expf(s2 - m), e3 = expf(s3 - m);
    float inv = 1.f / (e0 + e1 + e2 + e3);

    float ox = (e0 * vs[0].x + e1 * vs[1].x + e2 * vs[2].x + e3 * vs[3].x) * inv;
    float oy = (e0 * vs[0].y + e1 * vs[1].y + e2 * vs[2].y + e3 * vs[3].y) * inv;
    float2 o = make_float2(__uint_as_float(f2tf(ox)), __uint_as_float(f2tf(oy)));
    *(float2*)(out + (size_t)bl * DM + h * D_ + 2 * lane) = o;
}

// ---------------------------------------------------------------------------
extern "C" void kernel_launch(void* const* d_in, const int* in_sizes, int n_in,
                              void* d_out, int out_size)
{
    const float* q_in  = (const float*)d_in[0];
    const float* kv_in = (const float*)d_in[1];
    const float* Wq    = (const float*)d_in[2];
    const float* bq    = (const float*)d_in[3];
    const float* Wk    = (const float*)d_in[4];
    const float* bk    = (const float*)d_in[5];
    const float* Wv    = (const float*)d_in[6];
    const float* bv    = (const float*)d_in[7];
    const float* Woff  = (const float*)d_in[8];
    const float* boff  = (const float*)d_in[9];
    const float* Wa    = (const float*)d_in[10];
    const float* ba    = (const float*)d_in[11];
    const float* Wo    = (const float*)d_in[12];
    const float* bo    = (const float*)d_in[13];

    float *qoab, *kvb, *ab, *wqoa, *wkv, *wot, *bqoa, *bkv;
    cudaGetSymbolAddress((void**)&qoab, g_qoa);
    cudaGetSymbolAddress((void**)&kvb,  g_kv);
    cudaGetSymbolAddress((void**)&ab,   g_attn);
    cudaGetSymbolAddress((void**)&wqoa, g_Wqoa);
    cudaGetSymbolAddress((void**)&wkv,  g_Wkv);
    cudaGetSymbolAddress((void**)&wot,  g_Wo_t);
    cudaGetSymbolAddress((void**)&bqoa, g_bqoa);
    cudaGetSymbolAddress((void**)&bkv,  g_bkv);

    cudaFuncSetAttribute(gemm_dual,
                         cudaFuncAttributeMaxDynamicSharedMemorySize, DYN_SMEM);
    cudaFuncSetAttribute(gemm_out,
                         cudaFuncAttributeMaxDynamicSharedMemorySize, DYN_SMEM);

    // One fused prologue launch: all weight conversions + bias copies
    prep<<<(PRE_TOTAL + 255) / 256, 256>>>(
        wqoa, wkv, wot, bqoa, bkv,
        Wq, Woff, Wa, Wk, Wv, Wo, bq, boff, ba, bk, bv);

    // Merged projection GEMMs: x<5 -> qoa (N=576), x>=5 -> kv (N=1024)
    dim3 gDual(13, MTOT / BM);
    gemm_dual<<<gDual, 256, DYN_SMEM>>>(q_in, kv_in, wqoa, wkv, bqoa, bkv,
                                        qoab, kvb);

    attn_kernel<<<(MTOT * H_) / 8, 256>>>(qoab, kvb, ab);

    dim3 gOut(DM / BN, MTOT / BM);
    gemm_out<<<gOut, 256, DYN_SMEM>>>(ab, wot, bo, (float*)d_out);
}

// round 17
// speedup vs baseline: 4.3241x; 1.0517x over previous
#include <cuda_runtime.h>
#include <math.h>
#include <stdint.h>

// Problem constants (fixed by setup_inputs)
#define B_  4
#define L_  4096
#define DM  512
#define H_  8
#define P_  4
#define D_  64
#define MTOT (B_*L_)   // 16384

#define NQOA 576       // Wq | Woff | Wa fused output cols
#define NKV  1024      // Wk | Wv fused output cols

// GEMM tiling: CTA 128x128x32, 256 threads = 8 warps (4m x 2n), warp tile 32x64
#define BM 128
#define BN 128
#define BK 32
#define NSTAGES 3
#define KTILES (DM/BK)          // 16
#define LDSA (BK + 4)           // 36 floats per smem row (conflict-free for LDSM)
#define ATILE (BM * LDSA)
#define BTILE (BN * LDSA)
#define STAGEF (ATILE + BTILE)  // 9216 floats
#define DYN_SMEM (NSTAGES * STAGEF * 4)  // 110592 B -> 2 CTAs/SM

// Scratch (no cudaMalloc allowed)
__device__ float g_qoa [(size_t)MTOT*NQOA];
__device__ float g_kv  [(size_t)MTOT*NKV];
__device__ float g_attn[(size_t)MTOT*DM];
__device__ float g_Wqoa[640*DM];
__device__ float g_Wkv [NKV*DM];
__device__ float g_Wo_t[DM*DM];
__device__ float g_bqoa[640];
__device__ float g_bkv [NKV];

// ---------------------------------------------------------------------------
__device__ __forceinline__ uint32_t smem_u32(const void* p) {
    uint32_t a;
    asm("{ .reg .u64 t; cvta.to.shared.u64 t, %1; cvt.u32.u64 %0, t; }"
        : "=r"(a) : "l"(p));
    return a;
}

__device__ __forceinline__ void cp16(uint32_t dst, const float* src, uint32_t sz) {
    asm volatile("cp.async.cg.shared.global [%0], [%1], 16, %2;\n"
                 :: "r"(dst), "l"(src), "r"(sz));
}

// round-to-nearest fp32 -> tf32 (zero-mean rounding error)
__device__ __forceinline__ uint32_t f2tf(float x) {
    uint32_t r;
    asm("cvt.rna.tf32.f32 %0, %1;" : "=r"(r) : "f"(x));
    return r;
}

__device__ __forceinline__ void mma_tf32(float* c, const uint32_t* a,
                                         uint32_t b0, uint32_t b1) {
    asm volatile(
        "mma.sync.aligned.m16n8k8.row.col.f32.tf32.tf32.f32 "
        "{%0,%1,%2,%3}, {%4,%5,%6,%7}, {%8,%9}, {%0,%1,%2,%3};"
        : "+f"(c[0]), "+f"(c[1]), "+f"(c[2]), "+f"(c[3])
        : "r"(a[0]), "r"(a[1]), "r"(a[2]), "r"(a[3]), "r"(b0), "r"(b1));
}

// ldmatrix x4: 4 8x8-b16 matrices; for tf32, an 8x8 f32 tile = 8 rows x 16B.
// Thread t receives, per matrix j (-> reg j), f32 element (row t/4, col t%4).
__device__ __forceinline__ void ldsm4(uint32_t* r, uint32_t addr) {
    asm volatile("ldmatrix.sync.aligned.m8n8.x4.shared.b16 {%0,%1,%2,%3}, [%4];"
                 : "=r"(r[0]), "=r"(r[1]), "=r"(r[2]), "=r"(r[3]) : "r"(addr));
}

// ---------------------------------------------------------------------------
// Fused prologue: tf32-convert all weights into fused buffers + copy biases.
// ---------------------------------------------------------------------------
#define PRE_TOTAL 270736
__device__ __forceinline__ float4 cv4(float4 v) {
    return make_float4(__uint_as_float(f2tf(v.x)), __uint_as_float(f2tf(v.y)),
                       __uint_as_float(f2tf(v.z)), __uint_as_float(f2tf(v.w)));
}
__global__ __launch_bounds__(256) void prep(
    float* __restrict__ wqoa, float* __restrict__ wkv, float* __restrict__ wot,
    float* __restrict__ bqoa, float* __restrict__ bkv,
    const float* __restrict__ Wq, const float* __restrict__ Woff,
    const float* __restrict__ Wa, const float* __restrict__ Wk,
    const float* __restrict__ Wv, const float* __restrict__ Wo,
    const float* __restrict__ bq, const float* __restrict__ boff,
    const float* __restrict__ ba, const float* __restrict__ bk,
    const float* __restrict__ bv)
{
    int i = blockIdx.x * blockDim.x + threadIdx.x;
    if (i >= PRE_TOTAL) return;
    if (i < 270336) {
        const float* src; float* dst; int d;
        if      (i <  65536) { src = Wq;   dst = wqoa;                d = i; }
        else if (i <  69632) { src = Woff; dst = wqoa + 65536*4;      d = i - 65536; }
        else if (i <  73728) { src = Wa;   dst = wqoa + 69632*4;      d = i - 69632; }
        else if (i < 139264) { src = Wk;   dst = wkv;                 d = i - 73728; }
        else if (i < 204800) { src = Wv;   dst = wkv + 65536*4;       d = i - 139264; }
        else                 { src = Wo;   dst = wot;                 d = i - 204800; }
        ((float4*)dst)[d] = cv4(((const float4*)src)[d]);
    } else {
        int j = i - 270336;
        const float* src; float* dst; int d;
        if      (j < 128) { src = bq;   dst = bqoa;            d = j; }
        else if (j < 136) { src = boff; dst = bqoa + 512;      d = j - 128; }
        else if (j < 144) { src = ba;   dst = bqoa + 544;      d = j - 136; }
        else if (j < 272) { src = bk;   dst = bkv;             d = j - 144; }
        else              { src = bv;   dst = bkv + 512;       d = j - 272; }
        ((float4*)dst)[d] = ((const float4*)src)[d];
    }
}

// ---------------------------------------------------------------------------
// GEMM body: C[M,N] = A[M,512] @ W[N,512]^T + bias[N] via mma.sync tf32.
// CTA: 128x128 tile, 256 threads = 8 warps (4m x 2n), warp tile 32x64.
// cp.async 3-stage pipeline; fragments loaded via ldmatrix.x4 (4x fewer
// shared-mem instructions than scalar LDS).
// ---------------------------------------------------------------------------
template<bool CONVA>
__device__ __forceinline__ void gemm_body(
    const float* __restrict__ A, const float* __restrict__ W,
    const float* __restrict__ bias, float* __restrict__ C,
    int N, int n0, int m0, float* sm)
{
    const int tid    = threadIdx.x;
    const int lane   = tid & 31;
    const int wid    = tid >> 5;       // 0..7
    const int warp_m = wid >> 1;       // 0..3 -> *32
    const int warp_n = wid & 1;        // 0..1 -> *64
    const int r      = lane >> 2;      // 0..7
    const int c      = lane & 3;       // 0..3
    const int lr     = lane & 7;       // ldmatrix row within group
    const int g      = lane >> 3;      // ldmatrix matrix-group 0..3

    float acc[2][8][4];
#pragma unroll
    for (int i = 0; i < 2; i++)
#pragma unroll
        for (int j = 0; j < 8; j++)
#pragma unroll
            for (int q = 0; q < 4; q++) acc[i][j][q] = 0.f;

    const uint32_t smb = smem_u32(sm);

    // Per-thread LDSM byte offsets relative to stage base.
    // A, mf: matrices {(row+0,k0),(row+8,k0),(row+0,k0+4),(row+8,k0+4)}
    //   -> row_add = (g&1)*8, col_add = (g>>1)*4
    uint32_t aoff[2], boff[4];
#pragma unroll
    for (int mf = 0; mf < 2; mf++)
        aoff[mf] = (uint32_t)(((warp_m * 32 + mf * 16 + (g & 1) * 8 + lr) * LDSA
                               + (g >> 1) * 4) * 4);
    // B, p (nf pair): matrices {(row+0,k0),(row+0,k0+4),(row+8,k0),(row+8,k0+4)}
    //   -> row_add = (g>>1)*8, col_add = (g&1)*4
    //   regs: r0=b0(nf=2p), r1=b1(nf=2p), r2=b0(nf=2p+1), r3=b1(nf=2p+1)
#pragma unroll
    for (int p = 0; p < 4; p++)
        boff[p] = (uint32_t)(ATILE * 4
                  + ((warp_n * 64 + p * 16 + (g >> 1) * 8 + lr) * LDSA
                     + (g & 1) * 4) * 4);

    auto load_tile = [&](int t) {
        const int s = t % NSTAGES;
        const uint32_t sa = smb + (uint32_t)(s * STAGEF) * 4u;
        const uint32_t sb = sa + (uint32_t)ATILE * 4u;
        const int k0 = t * BK;
#pragma unroll
        for (int i = 0; i < 4; i++) {
            const int idx = tid + i * 256;       // 0..1023
            const int row = idx >> 3;
            const int kc  = (idx & 7) * 4;
            cp16(sa + (uint32_t)(row * LDSA + kc) * 4u,
                 A + (size_t)(m0 + row) * DM + k0 + kc, 16u);
            const int wr = n0 + row;
            const float* bsrc = W + (size_t)(wr < N ? wr : 0) * DM + k0 + kc;
            cp16(sb + (uint32_t)(row * LDSA + kc) * 4u, bsrc, wr < N ? 16u : 0u);
        }
        asm volatile("cp.async.commit_group;\n");
    };

#pragma unroll
    for (int t = 0; t < NSTAGES - 1; t++) load_tile(t);

    for (int t = 0; t < KTILES; t++) {
        asm volatile("cp.async.wait_group %0;\n" :: "n"(NSTAGES - 2));
        __syncthreads();

        if (t + NSTAGES - 1 < KTILES) load_tile(t + NSTAGES - 1);
        else asm volatile("cp.async.commit_group;\n");

        const uint32_t sbase = smb + (uint32_t)((t % NSTAGES) * STAGEF) * 4u;

#pragma unroll
        for (int ks = 0; ks < 4; ks++) {
            const uint32_t kb = (uint32_t)(ks * 8 * 4);   // k0 bytes
            uint32_t af[2][4];
            ldsm4(af[0], sbase + aoff[0] + kb);
            ldsm4(af[1], sbase + aoff[1] + kb);
            if (CONVA) {
#pragma unroll
                for (int mf = 0; mf < 2; mf++)
#pragma unroll
                    for (int q = 0; q < 4; q++)
                        af[mf][q] = f2tf(__uint_as_float(af[mf][q]));
            }
            uint32_t bf[4][4];
#pragma unroll
            for (int p = 0; p < 4; p++)
                ldsm4(bf[p], sbase + boff[p] + kb);
#pragma unroll
            for (int p = 0; p < 4; p++) {
                mma_tf32(acc[0][2*p    ], af[0], bf[p][0], bf[p][1]);
                mma_tf32(acc[1][2*p    ], af[1], bf[p][0], bf[p][1]);
                mma_tf32(acc[0][2*p + 1], af[0], bf[p][2], bf[p][3]);
                mma_tf32(acc[1][2*p + 1], af[1], bf[p][2], bf[p][3]);
            }
        }
        // no bottom sync: top sync of next iter protects stage reuse
    }

    // epilogue: bias + store
#pragma unroll
    for (int mf = 0; mf < 2; mf++) {
        const int row0 = m0 + warp_m * 32 + mf * 16 + r;
#pragma unroll
        for (int nf = 0; nf < 8; nf++) {
            const int col = n0 + warp_n * 64 + nf * 8 + c * 2;
            if (col < N) {
                const float bx = bias[col], by = bias[col + 1];
                float2 o0 = make_float2(acc[mf][nf][0] + bx, acc[mf][nf][1] + by);
                float2 o1 = make_float2(acc[mf][nf][2] + bx, acc[mf][nf][3] + by);
                *(float2*)(C + (size_t)row0 * N + col)       = o0;
                *(float2*)(C + (size_t)(row0 + 8) * N + col) = o1;
            }
        }
    }
}

// Fused launch: blockIdx.x < 5 -> qoa GEMM (A=q_in), else kv GEMM (A=kv_in)
__global__ __launch_bounds__(256, 2) void gemm_dual(
    const float* __restrict__ Aq, const float* __restrict__ Akv,
    const float* __restrict__ Wqoa_, const float* __restrict__ Wkv_,
    const float* __restrict__ bqoa_, const float* __restrict__ bkv_,
    float* __restrict__ Cqoa, float* __restrict__ Ckv)
{
    extern __shared__ float sm[];
    const int x  = blockIdx.x;
    const int m0 = blockIdx.y * BM;
    if (x < 5) {
        gemm_body<true>(Aq, Wqoa_, bqoa_, Cqoa, NQOA, x * BN, m0, sm);
    } else {
        gemm_body<true>(Akv, Wkv_, bkv_, Ckv, NKV, (x - 5) * BN, m0, sm);
    }
}

__global__ __launch_bounds__(256, 2) void gemm_out(
    const float* __restrict__ A, const float* __restrict__ W,
    const float* __restrict__ bias, float* __restrict__ C)
{
    extern __shared__ float sm[];
    gemm_body<false>(A, W, bias, C, DM, blockIdx.x * BN, blockIdx.y * BM, sm);
}

// ---------------------------------------------------------------------------
// Deformable attention. One warp per (b,l,h); lane owns a float2 of D=64.
// qoa: [M, 576] = q | offsets | logits.  kv: [M, 1024] = k | v.
// Output written tf32-rounded (feeds Wo GEMM with CONVA=false).
// ---------------------------------------------------------------------------
__global__ __launch_bounds__(256) void attn_kernel(
    const float* __restrict__ qoa, const float* __restrict__ kv,
    float* __restrict__ out)
{
    const int gw   = (blockIdx.x * blockDim.x + threadIdx.x) >> 5;
    const int lane = threadIdx.x & 31;
    const int h    = gw & (H_ - 1);
    const int bl   = gw >> 3;          // b*L + l
    const int l    = bl & (L_ - 1);
    const int brow = bl - l;           // b*L

    const float2 qd = *(const float2*)(qoa + (size_t)bl * NQOA + h * D_ + 2 * lane);
    const float* op = qoa + (size_t)bl * NQOA + 512 + h * P_;
    const float* lp = op + 32;

    float  dots[P_];
    float2 vs[P_];

#pragma unroll
    for (int p = 0; p < P_; p++) {
        float pos = (float)l + op[p];
        pos = fminf(fmaxf(pos, 0.f), (float)(L_ - 1));
        float fi = floorf(pos);
        int   i0 = (int)fi;
        int   i1 = min(i0 + 1, L_ - 1);
        float w  = pos - fi;

        const float* row0 = kv + (size_t)(brow + i0) * NKV + h * D_ + 2 * lane;
        const float* row1 = kv + (size_t)(brow + i1) * NKV + h * D_ + 2 * lane;
        float2 k0 = *(const float2*)(row0);
        float2 k1 = *(const float2*)(row1);
        float2 v0 = *(const float2*)(row0 + 512);
        float2 v1 = *(const float2*)(row1 + 512);

        float2 ks;
        ks.x = (1.f - w) * k0.x + w * k1.x;
        ks.y = (1.f - w) * k0.y + w * k1.y;
        vs[p].x = (1.f - w) * v0.x + w * v1.x;
        vs[p].y = (1.f - w) * v0.y + w * v1.y;

        float d = qd.x * ks.x + qd.y * ks.y;
#pragma unroll
        for (int s = 16; s > 0; s >>= 1)
            d += __shfl_xor_sync(0xffffffffu, d, s);
        dots[p] = d;
    }

    float s0 = dots[0] * 0.125f + lp[0];
    float s1 = dots[1] * 0.125f + lp[1];
    float s2 = dots[2] * 0.125f + lp[2];
    float s3 = dots[3] * 0.125f + lp[3];
    float m  = fmaxf(fmaxf(s0, s1), fmaxf(s2, s3));
    float e0 = expf(s0 - m), e1 = expf(s1 - m);
    float e2 = expf(s2 - m), e3 = expf(s3 - m);
    float inv = 1.f / (e0 + e1 + e2 + e3);

    float ox = (e0 * vs[0].x + e1 * vs[1].x + e2 * vs[2].x + e3 * vs[3].x) * inv;
    float oy = (e0 * vs[0].y + e1 * vs[1].y + e2 * vs[2].y + e3 * vs[3].y) * inv;
    float2 o = make_float2(__uint_as_float(f2tf(ox)), __uint_as_float(f2tf(oy)));
    *(float2*)(out + (size_t)bl * DM + h * D_ + 2 * lane) = o;
}

// ---------------------------------------------------------------------------
extern "C" void kernel_launch(void* const* d_in, const int* in_sizes, int n_in,
                              void* d_out, int out_size)
{
    const float* q_in  = (const float*)d_in[0];
    const float* kv_in = (const float*)d_in[1];
    const float* Wq    = (const float*)d_in[2];
    const float* bq    = (const float*)d_in[3];
    const float* Wk    = (const float*)d_in[4];
    const float* bk    = (const float*)d_in[5];
    const float* Wv    = (const float*)d_in[6];
    const float* bv    = (const float*)d_in[7];
    const float* Woff  = (const float*)d_in[8];
    const float* boff  = (const float*)d_in[9];
    const float* Wa    = (const float*)d_in[10];
    const float* ba    = (const float*)d_in[11];
    const float* Wo    = (const float*)d_in[12];
    const float* bo    = (const float*)d_in[13];

    float *qoab, *kvb, *ab, *wqoa, *wkv, *wot, *bqoa, *bkv;
    cudaGetSymbolAddress((void**)&qoab, g_qoa);
    cudaGetSymbolAddress((void**)&kvb,  g_kv);
    cudaGetSymbolAddress((void**)&ab,   g_attn);
    cudaGetSymbolAddress((void**)&wqoa, g_Wqoa);
    cudaGetSymbolAddress((void**)&wkv,  g_Wkv);
    cudaGetSymbolAddress((void**)&wot,  g_Wo_t);
    cudaGetSymbolAddress((void**)&bqoa, g_bqoa);
    cudaGetSymbolAddress((void**)&bkv,  g_bkv);

    cudaFuncSetAttribute(gemm_dual,
                         cudaFuncAttributeMaxDynamicSharedMemorySize, DYN_SMEM);
    cudaFuncSetAttribute(gemm_out,
                         cudaFuncAttributeMaxDynamicSharedMemorySize, DYN_SMEM);

    // One fused prologue launch: all weight conversions + bias copies
    prep<<<(PRE_TOTAL + 255) / 256, 256>>>(
        wqoa, wkv, wot, bqoa, bkv,
        Wq, Woff, Wa, Wk, Wv, Wo, bq, boff, ba, bk, bv);

    // Merged projection GEMMs: x<5 -> qoa (N=576), x>=5 -> kv (N=1024)
    dim3 gDual(13, MTOT / BM);
    gemm_dual<<<gDual, 256, DYN_SMEM>>>(q_in, kv_in, wqoa, wkv, bqoa, bkv,
                                        qoab, kvb);

    attn_kernel<<<(MTOT * H_) / 8, 256>>>(qoab, kvb, ab);

    dim3 gOut(DM / BN, MTOT / BM);
    gemm_out<<<gOut, 256, DYN_SMEM>>>(ab, wot, bo, (float*)d_out);
}